// round 1
// baseline (speedup 1.0000x reference)
#include <cuda_runtime.h>
#include <cuda_bf16.h>
#include <math.h>

// ---------------- problem constants ----------------
#define S_   1024
#define H_   4096
#define NH_  32
#define NKV_ 8
#define HD_  128
#define NREP_ 4        // NH/NKV
#define IS_  11008
#define L_   2
#define EPS_ 1e-5f

// ---------------- scratch (device globals; no runtime alloc allowed) -------
__device__ float g_n   [(size_t)S_ * H_];                 // rmsnorm output
__device__ float g_q   [(size_t)S_ * H_];                 // Q (pre/post rope)
__device__ float g_kv  [(size_t)2 * S_ * NKV_ * HD_];     // K then V scratch
__device__ float g_sc  [(size_t)NH_ * S_ * S_];           // attention scores (128MB)
__device__ float g_at  [(size_t)S_ * H_];                 // attn output (S, NH*HD)
__device__ float g_ga  [(size_t)S_ * IS_];                // gate
__device__ float g_up  [(size_t)S_ * IS_];                // up

// ---------------- GEMM: C[M,N] (+)= A[M,K] * B[N,K]^T  (both K-contiguous) --
// BM=BN=128, BK=8, 256 threads, 8x8 micro tiles. Batched over z with strides;
// B's z index is z/zdiv (GQA head sharing).
#define BM 128
#define BN 128
#define BKK 8
#define TM 8
#define TN 8

template<bool ACCUM>
__global__ __launch_bounds__(256)
void gemm_nt_k(const float* __restrict__ A, int lda, long long sAz,
               const float* __restrict__ B, int ldb, long long sBz, int zdiv,
               float* __restrict__ C, int ldc, long long sCz,
               int K)
{
    __shared__ float As[BKK][BM];
    __shared__ float Bs[BKK][BN];
    const int z = blockIdx.z;
    A += (long long)blockIdx.y * BM * lda + (long long)z * sAz;
    B += (long long)blockIdx.x * BN * ldb + (long long)(z / zdiv) * sBz;
    C += (long long)blockIdx.y * BM * ldc + (long long)blockIdx.x * BN
       + (long long)z * sCz;

    const int tid = threadIdx.x;
    const int lr = tid >> 1;            // 0..127 (tile row to load)
    const int lc = (tid & 1) << 2;      // 0 or 4 (k offset, float4)
    const int tr = (tid >> 4) << 3;     // thread micro-tile row base
    const int tc = (tid & 15) << 3;     // thread micro-tile col base

    float acc[TM][TN] = {};

    for (int k0 = 0; k0 < K; k0 += BKK) {
        float4 a4 = *reinterpret_cast<const float4*>(A + (long long)lr * lda + k0 + lc);
        float4 b4 = *reinterpret_cast<const float4*>(B + (long long)lr * ldb + k0 + lc);
        As[lc + 0][lr] = a4.x; As[lc + 1][lr] = a4.y;
        As[lc + 2][lr] = a4.z; As[lc + 3][lr] = a4.w;
        Bs[lc + 0][lr] = b4.x; Bs[lc + 1][lr] = b4.y;
        Bs[lc + 2][lr] = b4.z; Bs[lc + 3][lr] = b4.w;
        __syncthreads();
        #pragma unroll
        for (int k = 0; k < BKK; k++) {
            float4 a0 = *reinterpret_cast<const float4*>(&As[k][tr]);
            float4 a1 = *reinterpret_cast<const float4*>(&As[k][tr + 4]);
            float4 b0 = *reinterpret_cast<const float4*>(&Bs[k][tc]);
            float4 b1 = *reinterpret_cast<const float4*>(&Bs[k][tc + 4]);
            float ar[8] = {a0.x,a0.y,a0.z,a0.w,a1.x,a1.y,a1.z,a1.w};
            float br[8] = {b0.x,b0.y,b0.z,b0.w,b1.x,b1.y,b1.z,b1.w};
            #pragma unroll
            for (int i = 0; i < TM; i++)
                #pragma unroll
                for (int j = 0; j < TN; j++)
                    acc[i][j] += ar[i] * br[j];
        }
        __syncthreads();
    }

    #pragma unroll
    for (int i = 0; i < TM; i++) {
        float* cr = C + (long long)(tr + i) * ldc + tc;
        #pragma unroll
        for (int j = 0; j < TN; j++) {
            if (ACCUM) cr[j] = cr[j] + acc[i][j];
            else       cr[j] = acc[i][j];
        }
    }
}

// ---------------- GEMM NN: C[M,N] = A[M,K] * B[K,N]  (B N-contiguous) -------
template<bool ACCUM>
__global__ __launch_bounds__(256)
void gemm_nn_k(const float* __restrict__ A, int lda, long long sAz,
               const float* __restrict__ B, int ldb, long long sBz, int zdiv,
               float* __restrict__ C, int ldc, long long sCz,
               int K)
{
    __shared__ float As[BKK][BM];
    __shared__ float Bs[BKK][BN];
    const int z = blockIdx.z;
    A += (long long)blockIdx.y * BM * lda + (long long)z * sAz;
    B += (long long)blockIdx.x * BN + (long long)(z / zdiv) * sBz;
    C += (long long)blockIdx.y * BM * ldc + (long long)blockIdx.x * BN
       + (long long)z * sCz;

    const int tid = threadIdx.x;
    const int lr = tid >> 1;
    const int lc = (tid & 1) << 2;
    const int lrB = tid >> 5;            // 0..7
    const int lcB = (tid & 31) << 2;     // 0..124
    const int tr = (tid >> 4) << 3;
    const int tc = (tid & 15) << 3;

    float acc[TM][TN] = {};

    for (int k0 = 0; k0 < K; k0 += BKK) {
        float4 a4 = *reinterpret_cast<const float4*>(A + (long long)lr * lda + k0 + lc);
        As[lc + 0][lr] = a4.x; As[lc + 1][lr] = a4.y;
        As[lc + 2][lr] = a4.z; As[lc + 3][lr] = a4.w;
        float4 b4 = *reinterpret_cast<const float4*>(B + (long long)(k0 + lrB) * ldb + lcB);
        *reinterpret_cast<float4*>(&Bs[lrB][lcB]) = b4;
        __syncthreads();
        #pragma unroll
        for (int k = 0; k < BKK; k++) {
            float4 a0 = *reinterpret_cast<const float4*>(&As[k][tr]);
            float4 a1 = *reinterpret_cast<const float4*>(&As[k][tr + 4]);
            float4 b0 = *reinterpret_cast<const float4*>(&Bs[k][tc]);
            float4 b1 = *reinterpret_cast<const float4*>(&Bs[k][tc + 4]);
            float ar[8] = {a0.x,a0.y,a0.z,a0.w,a1.x,a1.y,a1.z,a1.w};
            float br[8] = {b0.x,b0.y,b0.z,b0.w,b1.x,b1.y,b1.z,b1.w};
            #pragma unroll
            for (int i = 0; i < TM; i++)
                #pragma unroll
                for (int j = 0; j < TN; j++)
                    acc[i][j] += ar[i] * br[j];
        }
        __syncthreads();
    }

    #pragma unroll
    for (int i = 0; i < TM; i++) {
        float* cr = C + (long long)(tr + i) * ldc + tc;
        #pragma unroll
        for (int j = 0; j < TN; j++) {
            if (ACCUM) cr[j] = cr[j] + acc[i][j];
            else       cr[j] = acc[i][j];
        }
    }
}

// ---------------- RMSNorm ---------------------------------------------------
__global__ __launch_bounds__(256)
void rmsnorm_k(const float* __restrict__ h, const float* __restrict__ w,
               float* __restrict__ out)
{
    const int row = blockIdx.x;
    const float* hr = h + (size_t)row * H_;
    float ss = 0.f;
    for (int j = threadIdx.x; j < H_; j += 256) {
        float x = hr[j];
        ss += x * x;
    }
    // block reduce sum
    #pragma unroll
    for (int o = 16; o > 0; o >>= 1) ss += __shfl_xor_sync(0xffffffffu, ss, o);
    __shared__ float sm[8];
    if ((threadIdx.x & 31) == 0) sm[threadIdx.x >> 5] = ss;
    __syncthreads();
    float tot = sm[0];
    #pragma unroll
    for (int i = 1; i < 8; i++) tot += sm[i];
    float inv = rsqrtf(tot / (float)H_ + EPS_);
    float* orow = out + (size_t)row * H_;
    for (int j = threadIdx.x; j < H_; j += 256)
        orow[j] = w[j] * hr[j] * inv;
}

// ---------------- RoPE (Q in-place, K roped+packed, V packed) --------------
// q scratch:  [S, NH*HD]; kin/vin: [S, NKV*HD];
// keys_l/vals_l: [NKV, S, HD] (directly in d_out cache region)
__global__ __launch_bounds__(HD_)
void rope_pack_k(float* __restrict__ q,
                 const float* __restrict__ kin, const float* __restrict__ vin,
                 const int* __restrict__ pos,
                 const float* __restrict__ cos_t, const float* __restrict__ sin_t,
                 float* __restrict__ keys_l, float* __restrict__ vals_l)
{
    const int s = blockIdx.x;
    const int d = threadIdx.x;
    const int p = pos[s];
    const float c  = cos_t[(size_t)p * HD_ + d];
    const float sn = sin_t[(size_t)p * HD_ + d];
    const float sgn = (d < HD_ / 2) ? -1.f : 1.f;

    // Q in place
    for (int hh = 0; hh < NH_; hh++) {
        float* qp = q + (size_t)s * H_ + hh * HD_;
        float a = qp[d];
        float b = qp[d ^ (HD_ / 2)];
        __syncthreads();
        qp[d] = a * c + sgn * b * sn;
    }
    // K rope + pack, V pack
    for (int kv = 0; kv < NKV_; kv++) {
        const float* kp = kin + (size_t)s * NKV_ * HD_ + kv * HD_;
        const float* vp = vin + (size_t)s * NKV_ * HD_ + kv * HD_;
        float a = kp[d];
        float b = kp[d ^ (HD_ / 2)];
        size_t oidx = (size_t)kv * S_ * HD_ + (size_t)s * HD_ + d;
        keys_l[oidx] = a * c + sgn * b * sn;
        vals_l[oidx] = vp[d];
    }
}

// ---------------- softmax over score rows (scale + mask + softmax) ---------
__global__ __launch_bounds__(256)
void softmax_k(float* __restrict__ scores, const float* __restrict__ mask,
               float scale)
{
    const int q = blockIdx.x;
    const int h = blockIdx.y;
    float* row = scores + ((size_t)h * S_ + q) * (size_t)S_;
    const float* m = mask + (size_t)q * S_;

    float v[4];
    float mx = -1e30f;
    #pragma unroll
    for (int t = 0; t < 4; t++) {
        int j = threadIdx.x + t * 256;
        v[t] = row[j] * scale + m[j];
        mx = fmaxf(mx, v[t]);
    }
    #pragma unroll
    for (int o = 16; o > 0; o >>= 1) mx = fmaxf(mx, __shfl_xor_sync(0xffffffffu, mx, o));
    __shared__ float smx[8];
    __shared__ float ssum[8];
    if ((threadIdx.x & 31) == 0) smx[threadIdx.x >> 5] = mx;
    __syncthreads();
    float rmx = smx[0];
    #pragma unroll
    for (int i = 1; i < 8; i++) rmx = fmaxf(rmx, smx[i]);

    float sum = 0.f;
    #pragma unroll
    for (int t = 0; t < 4; t++) {
        v[t] = expf(v[t] - rmx);
        sum += v[t];
    }
    #pragma unroll
    for (int o = 16; o > 0; o >>= 1) sum += __shfl_xor_sync(0xffffffffu, sum, o);
    if ((threadIdx.x & 31) == 0) ssum[threadIdx.x >> 5] = sum;
    __syncthreads();
    float rsum = ssum[0];
    #pragma unroll
    for (int i = 1; i < 8; i++) rsum += ssum[i];
    float inv = 1.f / rsum;
    #pragma unroll
    for (int t = 0; t < 4; t++) {
        int j = threadIdx.x + t * 256;
        row[j] = v[t] * inv;
    }
}

// ---------------- silu(gate) * up ------------------------------------------
__global__ __launch_bounds__(256)
void silu_mul_k(float* __restrict__ g, const float* __restrict__ u, long long n)
{
    long long i = (long long)blockIdx.x * 256 + threadIdx.x;
    if (i < n) {
        float x = g[i];
        g[i] = (x / (1.f + expf(-x))) * u[i];
    }
}

// ---------------- launch ----------------------------------------------------
extern "C" void kernel_launch(void* const* d_in, const int* in_sizes, int n_in,
                              void* d_out, int out_size)
{
    const float* x     = (const float*)d_in[0];
    const float* mask  = (const float*)d_in[1];
    const int*   pos   = (const int*)  d_in[2];
    const float* cos_t = (const float*)d_in[3];
    const float* sin_t = (const float*)d_in[4];
    const float* ln1   = (const float*)d_in[5];
    const float* ln2   = (const float*)d_in[6];
    const float* qw    = (const float*)d_in[7];
    const float* kw    = (const float*)d_in[8];
    const float* vw    = (const float*)d_in[9];
    const float* ow    = (const float*)d_in[10];
    const float* gw    = (const float*)d_in[11];
    const float* uw    = (const float*)d_in[12];
    const float* dw    = (const float*)d_in[13];

    float* out  = (float*)d_out;
    float* h    = out;                                   // hidden state lives in d_out
    float* keys = out + (size_t)S_ * H_;                 // [L, NKV, S, HD]
    float* vals = keys + (size_t)L_ * NKV_ * S_ * HD_;   // [L, NKV, S, HD]

    float *n_, *q_, *kv_, *sc_, *at_, *ga_, *up_;
    cudaGetSymbolAddress((void**)&n_,  g_n);
    cudaGetSymbolAddress((void**)&q_,  g_q);
    cudaGetSymbolAddress((void**)&kv_, g_kv);
    cudaGetSymbolAddress((void**)&sc_, g_sc);
    cudaGetSymbolAddress((void**)&at_, g_at);
    cudaGetSymbolAddress((void**)&ga_, g_ga);
    cudaGetSymbolAddress((void**)&up_, g_up);

    const float scale = 1.f / sqrtf((float)HD_);

    // h = x
    cudaMemcpyAsync(h, x, (size_t)S_ * H_ * sizeof(float),
                    cudaMemcpyDeviceToDevice, 0);

    for (int l = 0; l < L_; l++) {
        const float* qwl = qw + (size_t)l * (NH_ * HD_) * H_;
        const float* kwl = kw + (size_t)l * (NKV_ * HD_) * H_;
        const float* vwl = vw + (size_t)l * (NKV_ * HD_) * H_;
        const float* owl = ow + (size_t)l * H_ * (NH_ * HD_);
        const float* gwl = gw + (size_t)l * IS_ * H_;
        const float* uwl = uw + (size_t)l * IS_ * H_;
        const float* dwl = dw + (size_t)l * H_ * IS_;
        float* keys_l = keys + (size_t)l * NKV_ * S_ * HD_;
        float* vals_l = vals + (size_t)l * NKV_ * S_ * HD_;
        float* kscr = kv_;
        float* vscr = kv_ + (size_t)S_ * NKV_ * HD_;

        // ---- attention block ----
        rmsnorm_k<<<S_, 256>>>(h, ln1 + (size_t)l * H_, n_);

        gemm_nt_k<false><<<dim3(H_ / BN, S_ / BM, 1), 256>>>(
            n_, H_, 0, qwl, H_, 0, 1, q_, H_, 0, H_);
        gemm_nt_k<false><<<dim3((NKV_ * HD_) / BN, S_ / BM, 1), 256>>>(
            n_, H_, 0, kwl, H_, 0, 1, kscr, NKV_ * HD_, 0, H_);
        gemm_nt_k<false><<<dim3((NKV_ * HD_) / BN, S_ / BM, 1), 256>>>(
            n_, H_, 0, vwl, H_, 0, 1, vscr, NKV_ * HD_, 0, H_);

        rope_pack_k<<<S_, HD_>>>(q_, kscr, vscr, pos, cos_t, sin_t,
                                 keys_l, vals_l);

        // scores[h,q,k] = q_h . k_{h/4}
        gemm_nt_k<false><<<dim3(S_ / BN, S_ / BM, NH_), 256>>>(
            q_, H_, (long long)HD_,
            keys_l, HD_, (long long)S_ * HD_, NREP_,
            sc_, S_, (long long)S_ * S_, HD_);

        softmax_k<<<dim3(S_, NH_), 256>>>(sc_, mask, scale);

        // attn_out[q, h*HD+d] = P[h,q,:] @ V_{h/4}[:,d]
        gemm_nn_k<false><<<dim3(HD_ / BN, S_ / BM, NH_), 256>>>(
            sc_, S_, (long long)S_ * S_,
            vals_l, HD_, (long long)S_ * HD_, NREP_,
            at_, H_, (long long)HD_, S_);

        // h += attn_out @ o_w^T
        gemm_nt_k<true><<<dim3(H_ / BN, S_ / BM, 1), 256>>>(
            at_, H_, 0, owl, H_, 0, 1, h, H_, 0, H_);

        // ---- MLP block ----
        rmsnorm_k<<<S_, 256>>>(h, ln2 + (size_t)l * H_, n_);

        gemm_nt_k<false><<<dim3(IS_ / BN, S_ / BM, 1), 256>>>(
            n_, H_, 0, gwl, H_, 0, 1, ga_, IS_, 0, H_);
        gemm_nt_k<false><<<dim3(IS_ / BN, S_ / BM, 1), 256>>>(
            n_, H_, 0, uwl, H_, 0, 1, up_, IS_, 0, H_);

        long long nel = (long long)S_ * IS_;
        silu_mul_k<<<(unsigned)((nel + 255) / 256), 256>>>(ga_, up_, nel);

        // h += act @ down_w^T
        gemm_nt_k<true><<<dim3(H_ / BN, S_ / BM, 1), 256>>>(
            ga_, IS_, 0, dwl, IS_, 0, 1, h, H_, 0, IS_);
    }
}

// round 3
// speedup vs baseline: 1.9508x; 1.9508x over previous
#include <cuda_runtime.h>
#include <cuda_bf16.h>
#include <math.h>
#include <stdint.h>

// ---------------- problem constants ----------------
#define S_   1024
#define H_   4096
#define NH_  32
#define NKV_ 8
#define HD_  128
#define NREP_ 4        // NH/NKV
#define IS_  11008
#define L_   2
#define EPS_ 1e-5f

// ---------------- scratch (device globals; no runtime alloc allowed) -------
__device__ float g_n   [(size_t)S_ * H_];                 // rmsnorm output
__device__ float g_q   [(size_t)S_ * H_];                 // Q (pre/post rope)
__device__ float g_kv  [(size_t)2 * S_ * NKV_ * HD_];     // K then V scratch
__device__ float g_vt  [(size_t)NKV_ * HD_ * S_];         // V transposed [kv, d, s]
__device__ float g_sc  [(size_t)NH_ * S_ * S_];           // attention scores (128MB)
__device__ float g_at  [(size_t)S_ * H_];                 // attn output (S, NH*HD)
__device__ float g_ga  [(size_t)S_ * IS_];                // gate
__device__ float g_up  [(size_t)S_ * IS_];                // up

// =================== helpers ===============================================
__device__ __forceinline__ uint32_t smem_u32(const void* p) {
    uint32_t a;
    asm("{ .reg .u64 t; cvta.to.shared.u64 t, %1; cvt.u32.u64 %0, t; }"
        : "=r"(a) : "l"(p));
    return a;
}

__device__ __forceinline__ void ldm4(uint32_t* r, uint32_t addr) {
    asm volatile("ldmatrix.sync.aligned.m8n8.x4.shared.b16 {%0,%1,%2,%3}, [%4];"
        : "=r"(r[0]), "=r"(r[1]), "=r"(r[2]), "=r"(r[3]) : "r"(addr));
}

__device__ __forceinline__ void mma16816(float* c, const uint32_t* a,
                                         const uint32_t* b) {
    asm("mma.sync.aligned.m16n8k16.row.col.f32.bf16.bf16.f32 "
        "{%0,%1,%2,%3}, {%4,%5,%6,%7}, {%8,%9}, {%0,%1,%2,%3};"
        : "+f"(c[0]), "+f"(c[1]), "+f"(c[2]), "+f"(c[3])
        : "r"(a[0]), "r"(a[1]), "r"(a[2]), "r"(a[3]), "r"(b[0]), "r"(b[1]));
}

// split 8 fp32 -> 8 bf16 hi (packed uint4) + 8 bf16 lo (exact residual)
__device__ __forceinline__ void cvt_chunk(float4 f0, float4 f1,
                                          uint4& hi, uint4& lo) {
    float f[8] = {f0.x, f0.y, f0.z, f0.w, f1.x, f1.y, f1.z, f1.w};
    uint32_t h[4], l[4];
#pragma unroll
    for (int i = 0; i < 4; i++) {
        asm("cvt.rn.bf16x2.f32 %0, %1, %2;"
            : "=r"(h[i]) : "f"(f[2 * i + 1]), "f"(f[2 * i]));
        float h0 = __uint_as_float(h[i] << 16);
        float h1 = __uint_as_float(h[i] & 0xffff0000u);
        float r0 = f[2 * i] - h0;
        float r1 = f[2 * i + 1] - h1;
        asm("cvt.rn.bf16x2.f32 %0, %1, %2;"
            : "=r"(l[i]) : "f"(r1), "f"(r0));
    }
    hi = make_uint4(h[0], h[1], h[2], h[3]);
    lo = make_uint4(l[0], l[1], l[2], l[3]);
}

// ============ split-bf16 HMMA GEMM: C[M,N] (+)= A[M,K] * B[N,K]^T ==========
// CTA tile 128x128, K-tile 32, 2-stage pipelined smem (bf16 hi/lo planes).
// 8 warps (4 along M x 2 along N), warp tile 32x64, mma m16n8k16.
// grid = (Mtiles, Ntiles, Z); B z-index = z / zdiv (GQA sharing).
// smem per stage (32KB): Ah[128][32]b16, Al, Bh, Bl; swizzle: 16B chunk
// c -> c ^ ((row>>1)&3) within 64B row.
#define STAGE_B 32768
#define SMEM_DYN (2 * STAGE_B)

template<bool ACCUM>
__global__ __launch_bounds__(256, 1)
void gemm_mma(const float* __restrict__ A, int lda, long long sAz,
              const float* __restrict__ B, int ldb, long long sBz, int zdiv,
              float* __restrict__ C, int ldc, long long sCz, int K)
{
    extern __shared__ char dsm[];
    const uint32_t sb = smem_u32(dsm);
    const int tid = threadIdx.x;
    const int wid = tid >> 5, lid = tid & 31;
    const int wm = wid & 3, wn = wid >> 2;
    const int z = blockIdx.z;

    A += (long long)blockIdx.x * 128 * lda + (long long)z * sAz;
    B += (long long)blockIdx.y * 128 * ldb + (long long)(z / zdiv) * sBz;
    C += (long long)blockIdx.x * 128 * ldc + (long long)blockIdx.y * 128
       + (long long)z * sCz;

    // producer assignment: threads 0-127 -> A row tid; 128-255 -> B row tid-128
    const int prow = tid & 127;
    const float* srcBase = (tid < 128)
        ? (A + (long long)prow * lda)
        : (B + (long long)prow * ldb);
    const uint32_t planeA = (tid < 128) ? 0u : 16384u;  // Ah at 0, Bh at 16K
    // within stage: Ah 0, Al 8192, Bh 16384, Bl 24576
    const uint32_t rsw = ((uint32_t)(prow >> 1) & 3u);
    uint32_t stsOff[4];
#pragma unroll
    for (int c = 0; c < 4; c++)
        stsOff[c] = (uint32_t)prow * 64 + ((uint32_t)(c ^ rsw) << 4);

    float acc[2][8][4] = {};
    float4 st[8];

    const int nkt = K / 32;

    // prologue: load k-tile 0
#pragma unroll
    for (int i = 0; i < 8; i++)
        st[i] = *reinterpret_cast<const float4*>(srcBase + i * 4);
    {
        char* base = dsm + planeA;
#pragma unroll
        for (int c = 0; c < 4; c++) {
            uint4 hi, lo;
            cvt_chunk(st[2 * c], st[2 * c + 1], hi, lo);
            *reinterpret_cast<uint4*>(base + stsOff[c]) = hi;
            *reinterpret_cast<uint4*>(base + 8192 + stsOff[c]) = lo;
        }
    }
    __syncthreads();

    // precompute ldmatrix lane addresses (stage-0 based; add stage offset later)
    // A: per m-tile mt, per k16 s
    uint32_t aAddr[2][2], bAddr[2][4];
    {
        int j = lid >> 3, rin = lid & 7;
#pragma unroll
        for (int mt = 0; mt < 2; mt++) {
#pragma unroll
            for (int s = 0; s < 2; s++) {
                int row = wm * 32 + mt * 16 + (j & 1) * 8 + rin;
                int ch = 2 * s + (j >> 1);
                aAddr[mt][s] = sb + (uint32_t)row * 64
                             + ((uint32_t)(ch ^ ((row >> 1) & 3)) << 4);
            }
        }
#pragma unroll
        for (int q = 0; q < 4; q++) {   // covers n-tiles 2q, 2q+1
#pragma unroll
            for (int s = 0; s < 2; s++) {
                int row = wn * 64 + q * 16 + (j >> 1) * 8 + rin;
                int ch = 2 * s + (j & 1);
                bAddr[s][q] = sb + 16384u + (uint32_t)row * 64
                            + ((uint32_t)(ch ^ ((row >> 1) & 3)) << 4);
            }
        }
    }

    for (int kt = 0; kt < nkt; kt++) {
        const uint32_t stg = (uint32_t)(kt & 1) * STAGE_B;
        // prefetch next k-tile from gmem
        if (kt + 1 < nkt) {
            const float* src = srcBase + (kt + 1) * 32;
#pragma unroll
            for (int i = 0; i < 8; i++)
                st[i] = *reinterpret_cast<const float4*>(src + i * 4);
        }
        // compute on stage stg
#pragma unroll
        for (int s = 0; s < 2; s++) {
            uint32_t ah[2][4], al[2][4], bh[8][2], bl[8][2];
#pragma unroll
            for (int mt = 0; mt < 2; mt++) {
                ldm4(ah[mt], aAddr[mt][s] + stg);
                ldm4(al[mt], aAddr[mt][s] + stg + 8192u);
            }
#pragma unroll
            for (int q = 0; q < 4; q++) {
                uint32_t t4[4];
                ldm4(t4, bAddr[s][q] + stg);
                bh[2 * q][0] = t4[0]; bh[2 * q][1] = t4[1];
                bh[2 * q + 1][0] = t4[2]; bh[2 * q + 1][1] = t4[3];
                ldm4(t4, bAddr[s][q] + stg + 8192u);
                bl[2 * q][0] = t4[0]; bl[2 * q][1] = t4[1];
                bl[2 * q + 1][0] = t4[2]; bl[2 * q + 1][1] = t4[3];
            }
            // three passes so same-accumulator MMAs are far apart
#pragma unroll
            for (int nt = 0; nt < 8; nt++)
#pragma unroll
                for (int mt = 0; mt < 2; mt++)
                    mma16816(acc[mt][nt], ah[mt], bh[nt]);
#pragma unroll
            for (int nt = 0; nt < 8; nt++)
#pragma unroll
                for (int mt = 0; mt < 2; mt++)
                    mma16816(acc[mt][nt], ah[mt], bl[nt]);
#pragma unroll
            for (int nt = 0; nt < 8; nt++)
#pragma unroll
                for (int mt = 0; mt < 2; mt++)
                    mma16816(acc[mt][nt], al[mt], bh[nt]);
        }
        // store prefetched tile into the other stage
        if (kt + 1 < nkt) {
            char* base = dsm + (((kt + 1) & 1) * STAGE_B) + planeA;
#pragma unroll
            for (int c = 0; c < 4; c++) {
                uint4 hi, lo;
                cvt_chunk(st[2 * c], st[2 * c + 1], hi, lo);
                *reinterpret_cast<uint4*>(base + stsOff[c]) = hi;
                *reinterpret_cast<uint4*>(base + 8192 + stsOff[c]) = lo;
            }
        }
        __syncthreads();
    }

    // epilogue
    const int er = wm * 32 + (lid >> 2);
    const int ec = wn * 64 + 2 * (lid & 3);
#pragma unroll
    for (int mt = 0; mt < 2; mt++) {
#pragma unroll
        for (int nt = 0; nt < 8; nt++) {
            float* cp = C + (long long)(er + mt * 16) * ldc + ec + nt * 8;
            float2 v0 = make_float2(acc[mt][nt][0], acc[mt][nt][1]);
            float2 v1 = make_float2(acc[mt][nt][2], acc[mt][nt][3]);
            if (ACCUM) {
                float2 o0 = *reinterpret_cast<const float2*>(cp);
                float2 o1 = *reinterpret_cast<const float2*>(cp + 8 * ldc);
                v0.x += o0.x; v0.y += o0.y;
                v1.x += o1.x; v1.y += o1.y;
            }
            *reinterpret_cast<float2*>(cp) = v0;
            *reinterpret_cast<float2*>(cp + 8 * ldc) = v1;
        }
    }
}

// ---------------- RMSNorm ---------------------------------------------------
__global__ __launch_bounds__(256)
void rmsnorm_k(const float* __restrict__ h, const float* __restrict__ w,
               float* __restrict__ out)
{
    const int row = blockIdx.x;
    const float* hr = h + (size_t)row * H_;
    float ss = 0.f;
    for (int j = threadIdx.x; j < H_; j += 256) {
        float x = hr[j];
        ss += x * x;
    }
#pragma unroll
    for (int o = 16; o > 0; o >>= 1) ss += __shfl_xor_sync(0xffffffffu, ss, o);
    __shared__ float sm[8];
    if ((threadIdx.x & 31) == 0) sm[threadIdx.x >> 5] = ss;
    __syncthreads();
    float tot = sm[0];
#pragma unroll
    for (int i = 1; i < 8; i++) tot += sm[i];
    float inv = rsqrtf(tot / (float)H_ + EPS_);
    float* orow = out + (size_t)row * H_;
    for (int j = threadIdx.x; j < H_; j += 256)
        orow[j] = w[j] * hr[j] * inv;
}

// ---------------- RoPE (Q in-place, K roped+packed, V packed + V^T) --------
__global__ __launch_bounds__(HD_)
void rope_pack_k(float* __restrict__ q,
                 const float* __restrict__ kin, const float* __restrict__ vin,
                 const int* __restrict__ pos,
                 const float* __restrict__ cos_t, const float* __restrict__ sin_t,
                 float* __restrict__ keys_l, float* __restrict__ vals_l,
                 float* __restrict__ vt)
{
    const int s = blockIdx.x;
    const int d = threadIdx.x;
    const int p = pos[s];
    const float c  = cos_t[(size_t)p * HD_ + d];
    const float sn = sin_t[(size_t)p * HD_ + d];
    const float sgn = (d < HD_ / 2) ? -1.f : 1.f;

    for (int hh = 0; hh < NH_; hh++) {
        float* qp = q + (size_t)s * H_ + hh * HD_;
        float a = qp[d];
        float b = qp[d ^ (HD_ / 2)];
        __syncthreads();
        qp[d] = a * c + sgn * b * sn;
    }
    for (int kv = 0; kv < NKV_; kv++) {
        const float* kp = kin + (size_t)s * NKV_ * HD_ + kv * HD_;
        const float* vp = vin + (size_t)s * NKV_ * HD_ + kv * HD_;
        float a = kp[d];
        float b = kp[d ^ (HD_ / 2)];
        size_t oidx = (size_t)kv * S_ * HD_ + (size_t)s * HD_ + d;
        float vv = vp[d];
        keys_l[oidx] = a * c + sgn * b * sn;
        vals_l[oidx] = vv;
        vt[((size_t)kv * HD_ + d) * S_ + s] = vv;
    }
}

// ---------------- softmax (scale + mask + softmax) -------------------------
__global__ __launch_bounds__(256)
void softmax_k(float* __restrict__ scores, const float* __restrict__ mask,
               float scale)
{
    const int q = blockIdx.x;
    const int h = blockIdx.y;
    float* row = scores + ((size_t)h * S_ + q) * (size_t)S_;
    const float* m = mask + (size_t)q * S_;

    float v[4];
    float mx = -1e30f;
#pragma unroll
    for (int t = 0; t < 4; t++) {
        int j = threadIdx.x + t * 256;
        v[t] = row[j] * scale + m[j];
        mx = fmaxf(mx, v[t]);
    }
#pragma unroll
    for (int o = 16; o > 0; o >>= 1) mx = fmaxf(mx, __shfl_xor_sync(0xffffffffu, mx, o));
    __shared__ float smx[8];
    __shared__ float ssum[8];
    if ((threadIdx.x & 31) == 0) smx[threadIdx.x >> 5] = mx;
    __syncthreads();
    float rmx = smx[0];
#pragma unroll
    for (int i = 1; i < 8; i++) rmx = fmaxf(rmx, smx[i]);

    float sum = 0.f;
#pragma unroll
    for (int t = 0; t < 4; t++) {
        v[t] = expf(v[t] - rmx);
        sum += v[t];
    }
#pragma unroll
    for (int o = 16; o > 0; o >>= 1) sum += __shfl_xor_sync(0xffffffffu, sum, o);
    if ((threadIdx.x & 31) == 0) ssum[threadIdx.x >> 5] = sum;
    __syncthreads();
    float rsum = ssum[0];
#pragma unroll
    for (int i = 1; i < 8; i++) rsum += ssum[i];
    float inv = 1.f / rsum;
#pragma unroll
    for (int t = 0; t < 4; t++) {
        int j = threadIdx.x + t * 256;
        row[j] = v[t] * inv;
    }
}

// ---------------- silu(gate) * up ------------------------------------------
__global__ __launch_bounds__(256)
void silu_mul_k(float* __restrict__ g, const float* __restrict__ u, long long n)
{
    long long i = (long long)blockIdx.x * 256 + threadIdx.x;
    if (i < n) {
        float x = g[i];
        g[i] = (x / (1.f + expf(-x))) * u[i];
    }
}

// ---------------- launch ----------------------------------------------------
extern "C" void kernel_launch(void* const* d_in, const int* in_sizes, int n_in,
                              void* d_out, int out_size)
{
    const float* x     = (const float*)d_in[0];
    const float* mask  = (const float*)d_in[1];
    const int*   pos   = (const int*)  d_in[2];
    const float* cos_t = (const float*)d_in[3];
    const float* sin_t = (const float*)d_in[4];
    const float* ln1   = (const float*)d_in[5];
    const float* ln2   = (const float*)d_in[6];
    const float* qw    = (const float*)d_in[7];
    const float* kw    = (const float*)d_in[8];
    const float* vw    = (const float*)d_in[9];
    const float* ow    = (const float*)d_in[10];
    const float* gw    = (const float*)d_in[11];
    const float* uw    = (const float*)d_in[12];
    const float* dw    = (const float*)d_in[13];

    float* out  = (float*)d_out;
    float* h    = out;                                   // hidden state lives in d_out
    float* keys = out + (size_t)S_ * H_;                 // [L, NKV, S, HD]
    float* vals = keys + (size_t)L_ * NKV_ * S_ * HD_;   // [L, NKV, S, HD]

    float *n_, *q_, *kv_, *vt_, *sc_, *at_, *ga_, *up_;
    cudaGetSymbolAddress((void**)&n_,  g_n);
    cudaGetSymbolAddress((void**)&q_,  g_q);
    cudaGetSymbolAddress((void**)&kv_, g_kv);
    cudaGetSymbolAddress((void**)&vt_, g_vt);
    cudaGetSymbolAddress((void**)&sc_, g_sc);
    cudaGetSymbolAddress((void**)&at_, g_at);
    cudaGetSymbolAddress((void**)&ga_, g_ga);
    cudaGetSymbolAddress((void**)&up_, g_up);

    cudaFuncSetAttribute(gemm_mma<false>,
                         cudaFuncAttributeMaxDynamicSharedMemorySize, SMEM_DYN);
    cudaFuncSetAttribute(gemm_mma<true>,
                         cudaFuncAttributeMaxDynamicSharedMemorySize, SMEM_DYN);

    const float scale = 1.f / sqrtf((float)HD_);

    cudaMemcpyAsync(h, x, (size_t)S_ * H_ * sizeof(float),
                    cudaMemcpyDeviceToDevice, 0);

    for (int l = 0; l < L_; l++) {
        const float* qwl = qw + (size_t)l * (NH_ * HD_) * H_;
        const float* kwl = kw + (size_t)l * (NKV_ * HD_) * H_;
        const float* vwl = vw + (size_t)l * (NKV_ * HD_) * H_;
        const float* owl = ow + (size_t)l * H_ * (NH_ * HD_);
        const float* gwl = gw + (size_t)l * IS_ * H_;
        const float* uwl = uw + (size_t)l * IS_ * H_;
        const float* dwl = dw + (size_t)l * H_ * IS_;
        float* keys_l = keys + (size_t)l * NKV_ * S_ * HD_;
        float* vals_l = vals + (size_t)l * NKV_ * S_ * HD_;
        float* kscr = kv_;
        float* vscr = kv_ + (size_t)S_ * NKV_ * HD_;

        // ---- attention block ----
        rmsnorm_k<<<S_, 256>>>(h, ln1 + (size_t)l * H_, n_);

        gemm_mma<false><<<dim3(S_ / 128, H_ / 128, 1), 256, SMEM_DYN>>>(
            n_, H_, 0, qwl, H_, 0, 1, q_, H_, 0, H_);
        gemm_mma<false><<<dim3(S_ / 128, (NKV_ * HD_) / 128, 1), 256, SMEM_DYN>>>(
            n_, H_, 0, kwl, H_, 0, 1, kscr, NKV_ * HD_, 0, H_);
        gemm_mma<false><<<dim3(S_ / 128, (NKV_ * HD_) / 128, 1), 256, SMEM_DYN>>>(
            n_, H_, 0, vwl, H_, 0, 1, vscr, NKV_ * HD_, 0, H_);

        rope_pack_k<<<S_, HD_>>>(q_, kscr, vscr, pos, cos_t, sin_t,
                                 keys_l, vals_l, vt_);

        // scores[h,q,k] = q_h . k_{h/4}   (NT, K = HD)
        gemm_mma<false><<<dim3(S_ / 128, S_ / 128, NH_), 256, SMEM_DYN>>>(
            q_, H_, (long long)HD_,
            keys_l, HD_, (long long)S_ * HD_, NREP_,
            sc_, S_, (long long)S_ * S_, HD_);

        softmax_k<<<dim3(S_, NH_), 256>>>(sc_, mask, scale);

        // attn_out[q, h*HD+d] = P[h,q,:] . Vt_{h/4}[d,:]  (NT via V^T, K = S)
        gemm_mma<false><<<dim3(S_ / 128, HD_ / 128, NH_), 256, SMEM_DYN>>>(
            sc_, S_, (long long)S_ * S_,
            vt_, S_, (long long)HD_ * S_, NREP_,
            at_, H_, (long long)HD_, S_);

        // h += attn_out @ o_w^T
        gemm_mma<true><<<dim3(S_ / 128, H_ / 128, 1), 256, SMEM_DYN>>>(
            at_, H_, 0, owl, H_, 0, 1, h, H_, 0, H_);

        // ---- MLP block ----
        rmsnorm_k<<<S_, 256>>>(h, ln2 + (size_t)l * H_, n_);

        gemm_mma<false><<<dim3(S_ / 128, IS_ / 128, 1), 256, SMEM_DYN>>>(
            n_, H_, 0, gwl, H_, 0, 1, ga_, IS_, 0, H_);
        gemm_mma<false><<<dim3(S_ / 128, IS_ / 128, 1), 256, SMEM_DYN>>>(
            n_, H_, 0, uwl, H_, 0, 1, up_, IS_, 0, H_);

        long long nel = (long long)S_ * IS_;
        silu_mul_k<<<(unsigned)((nel + 255) / 256), 256>>>(ga_, up_, nel);

        // h += act @ down_w^T
        gemm_mma<true><<<dim3(S_ / 128, H_ / 128, 1), 256, SMEM_DYN>>>(
            ga_, IS_, 0, dwl, IS_, 0, 1, h, H_, 0, IS_);
    }
}

// round 4
// speedup vs baseline: 2.4044x; 1.2326x over previous
#include <cuda_runtime.h>
#include <cuda_bf16.h>
#include <math.h>
#include <stdint.h>

// ---------------- problem constants ----------------
#define S_   1024
#define H_   4096
#define NH_  32
#define NKV_ 8
#define HD_  128
#define NREP_ 4        // NH/NKV
#define IS_  11008
#define L_   2
#define EPS_ 1e-5f

// ---------------- scratch (device globals; no runtime alloc allowed) -------
__device__ float g_n   [(size_t)S_ * H_];                 // rmsnorm output
__device__ float g_q   [(size_t)S_ * H_];                 // Q (pre/post rope)
__device__ float g_kv  [(size_t)2 * S_ * NKV_ * HD_];     // K then V scratch
__device__ float g_vt  [(size_t)NKV_ * HD_ * S_];         // V transposed [kv, d, s]
__device__ float g_sc  [(size_t)NH_ * S_ * S_];           // attention scores (128MB)
__device__ float g_at  [(size_t)S_ * H_];                 // attn output (S, NH*HD)
__device__ float g_ga  [(size_t)S_ * IS_];                // gate
__device__ float g_up  [(size_t)S_ * IS_];                // up

// =================== helpers ===============================================
__device__ __forceinline__ uint32_t smem_u32(const void* p) {
    uint32_t a;
    asm("{ .reg .u64 t; cvta.to.shared.u64 t, %1; cvt.u32.u64 %0, t; }"
        : "=r"(a) : "l"(p));
    return a;
}

__device__ __forceinline__ void ldm4(uint32_t* r, uint32_t addr) {
    asm volatile("ldmatrix.sync.aligned.m8n8.x4.shared.b16 {%0,%1,%2,%3}, [%4];"
        : "=r"(r[0]), "=r"(r[1]), "=r"(r[2]), "=r"(r[3]) : "r"(addr));
}

__device__ __forceinline__ void mma16816(float* c, const uint32_t* a,
                                         const uint32_t* b) {
    asm("mma.sync.aligned.m16n8k16.row.col.f32.bf16.bf16.f32 "
        "{%0,%1,%2,%3}, {%4,%5,%6,%7}, {%8,%9}, {%0,%1,%2,%3};"
        : "+f"(c[0]), "+f"(c[1]), "+f"(c[2]), "+f"(c[3])
        : "r"(a[0]), "r"(a[1]), "r"(a[2]), "r"(a[3]), "r"(b[0]), "r"(b[1]));
}

// split 8 fp32 -> 8 bf16 hi (packed uint4) + 8 bf16 lo (exact residual)
__device__ __forceinline__ void cvt_chunk(float4 f0, float4 f1,
                                          uint4& hi, uint4& lo) {
    float f[8] = {f0.x, f0.y, f0.z, f0.w, f1.x, f1.y, f1.z, f1.w};
    uint32_t h[4], l[4];
#pragma unroll
    for (int i = 0; i < 4; i++) {
        asm("cvt.rn.bf16x2.f32 %0, %1, %2;"
            : "=r"(h[i]) : "f"(f[2 * i + 1]), "f"(f[2 * i]));
        float h0 = __uint_as_float(h[i] << 16);
        float h1 = __uint_as_float(h[i] & 0xffff0000u);
        float r0 = f[2 * i] - h0;
        float r1 = f[2 * i + 1] - h1;
        asm("cvt.rn.bf16x2.f32 %0, %1, %2;"
            : "=r"(l[i]) : "f"(r1), "f"(r0));
    }
    hi = make_uint4(h[0], h[1], h[2], h[3]);
    lo = make_uint4(l[0], l[1], l[2], l[3]);
}

// -------- mbarrier primitives (sm_80-level, valid on compute_103) ----------
#define MBAR_INIT(addr, cnt) \
    asm volatile("mbarrier.init.shared.b64 [%0], %1;" :: "r"(addr), "r"((uint32_t)(cnt)) : "memory")
#define MBAR_ARRIVE(addr) \
    asm volatile("mbarrier.arrive.shared.b64 _, [%0];" :: "r"(addr) : "memory")
#define MBAR_WAIT(mbar_addr, parity) do {                                        \
    uint32_t _m = (uint32_t)(mbar_addr);                                         \
    uint32_t _p = (uint32_t)(parity);                                            \
    uint32_t _done;                                                              \
    asm volatile("{\n\t.reg .pred p;\n\t"                                        \
        "mbarrier.try_wait.parity.acquire.cta.shared::cta.b64 p, [%1], %2;\n\t"  \
        "selp.b32 %0, 1, 0, p;\n\t}"                                             \
        : "=r"(_done) : "r"(_m), "r"(_p) : "memory");                            \
    if (!_done) {                                                                \
        asm volatile("{\n\t.reg .pred P1;\n\t"                                   \
            "WAIT_LOOP_%=:\n\t"                                                  \
            "mbarrier.try_wait.parity.acquire.cta.shared::cta.b64 P1, [%0], %1, 0x989680;\n\t" \
            "@P1 bra.uni WAIT_DONE_%=;\n\t"                                      \
            "bra.uni WAIT_LOOP_%=;\n\t"                                          \
            "WAIT_DONE_%=:\n\t}"                                                 \
            :: "r"(_m), "r"(_p) : "memory");                                     \
    }                                                                            \
} while (0)

// ============ warp-specialized split-bf16 HMMA GEMM ========================
// C[M,N] (+)= A[M,K] * B[N,K]^T. CTA tile 128x128, K-tile 32.
// 12 warps: 0-7 consumers (4x2, warp tile 32x64, mma m16n8k16),
//           8-11 producers (gmem fp32 -> bf16 hi/lo split -> swizzled smem).
// 4-stage smem ring, 32KB/stage: Ah@0 Al@8192 Bh@16384 Bl@24576,
// rows of 64B, 16B-chunk swizzle c ^= (row>>1)&3.
// grid = (Mtiles, Ntiles, Z); B z-index = z / zdiv (GQA sharing).
// Optional second problem (Balt/Calt) selected when z >= altz (altz>0).
#define NSTAGE 4
#define STAGE_B 32768
#define SMEM_DYN (NSTAGE * STAGE_B)

template<bool ACCUM>
__global__ __launch_bounds__(384, 1)
void gemm_ws(const float* __restrict__ A, int lda, long long sAz,
             const float* __restrict__ B, int ldb, long long sBz, int zdiv,
             float* __restrict__ C, int ldc, long long sCz, int K,
             const float* __restrict__ Balt, float* __restrict__ Calt, int altz)
{
    extern __shared__ char dsm[];
    __shared__ uint64_t mbar[2 * NSTAGE];   // full[0..3], empty[4..7]
    const uint32_t sb = smem_u32(dsm);
    const uint32_t mb = smem_u32(mbar);
    const int tid = threadIdx.x;
    const int wid = tid >> 5, lid = tid & 31;
    const int z = blockIdx.z;

    int zz = z;
    const float* Bp = B;
    float* Cp = C;
    if (altz && z >= altz) { Bp = Balt; Cp = Calt; zz = z - altz; }

    const float* Ap = A + (long long)blockIdx.x * 128 * lda + (long long)zz * sAz;
    Bp += (long long)blockIdx.y * 128 * ldb + (long long)(zz / zdiv) * sBz;
    Cp += (long long)blockIdx.x * 128 * ldc + (long long)blockIdx.y * 128
        + (long long)zz * sCz;

    if (tid == 0) {
#pragma unroll
        for (int i = 0; i < NSTAGE; i++) {
            MBAR_INIT(mb + 8 * i, 128);             // full: 128 producer threads
            MBAR_INIT(mb + 8 * (NSTAGE + i), 256);  // empty: 256 consumer threads
        }
    }
    __syncthreads();

    const int nkt = K / 32;

    if (wid >= 8) {
        // ================= producer =================
        const int prow = tid - 256;                 // 0..127
        const float* aRow = Ap + (long long)prow * lda;
        const float* bRow = Bp + (long long)prow * ldb;
        const uint32_t rsw = ((uint32_t)(prow >> 1) & 3u);
        uint32_t off[4];
#pragma unroll
        for (int c = 0; c < 4; c++)
            off[c] = (uint32_t)prow * 64 + (((uint32_t)c ^ rsw) << 4);

        for (int kt = 0; kt < nkt; kt++) {
            const int s = kt & (NSTAGE - 1);
            const int r = kt >> 2;
            if (r > 0) MBAR_WAIT(mb + 8 * (NSTAGE + s), (r - 1) & 1);
            char* base = dsm + (size_t)s * STAGE_B;
            const float* as = aRow + kt * 32;
            const float* bs = bRow + kt * 32;
            float4 av[8], bv[8];
#pragma unroll
            for (int i = 0; i < 8; i++) {
                av[i] = *reinterpret_cast<const float4*>(as + 4 * i);
                bv[i] = *reinterpret_cast<const float4*>(bs + 4 * i);
            }
#pragma unroll
            for (int c = 0; c < 4; c++) {
                uint4 hi, lo;
                cvt_chunk(av[2 * c], av[2 * c + 1], hi, lo);
                *reinterpret_cast<uint4*>(base + off[c]) = hi;
                *reinterpret_cast<uint4*>(base + 8192 + off[c]) = lo;
            }
#pragma unroll
            for (int c = 0; c < 4; c++) {
                uint4 hi, lo;
                cvt_chunk(bv[2 * c], bv[2 * c + 1], hi, lo);
                *reinterpret_cast<uint4*>(base + 16384 + off[c]) = hi;
                *reinterpret_cast<uint4*>(base + 24576 + off[c]) = lo;
            }
            MBAR_ARRIVE(mb + 8 * s);
        }
        return;
    }

    // ================= consumer =================
    const int wm = wid & 3, wn = wid >> 2;
    float acc[2][8][4] = {};

    // ldmatrix lane addresses (stage-0 based)
    uint32_t aAddr[2][2], bAddr[2][4];
    {
        int j = lid >> 3, rin = lid & 7;
#pragma unroll
        for (int mt = 0; mt < 2; mt++) {
#pragma unroll
            for (int s = 0; s < 2; s++) {
                int row = wm * 32 + mt * 16 + (j & 1) * 8 + rin;
                int ch = 2 * s + (j >> 1);
                aAddr[mt][s] = sb + (uint32_t)row * 64
                             + ((uint32_t)(ch ^ ((row >> 1) & 3)) << 4);
            }
        }
#pragma unroll
        for (int q = 0; q < 4; q++) {
#pragma unroll
            for (int s = 0; s < 2; s++) {
                int row = wn * 64 + q * 16 + (j >> 1) * 8 + rin;
                int ch = 2 * s + (j & 1);
                bAddr[s][q] = sb + 16384u + (uint32_t)row * 64
                            + ((uint32_t)(ch ^ ((row >> 1) & 3)) << 4);
            }
        }
    }

    for (int kt = 0; kt < nkt; kt++) {
        const int s = kt & (NSTAGE - 1);
        const uint32_t stg = (uint32_t)s * STAGE_B;
        MBAR_WAIT(mb + 8 * s, (kt >> 2) & 1);

#pragma unroll
        for (int s16 = 0; s16 < 2; s16++) {
            uint32_t ah[2][4], al[2][4], bh[8][2], bl[8][2];
#pragma unroll
            for (int mt = 0; mt < 2; mt++) {
                ldm4(ah[mt], aAddr[mt][s16] + stg);
                ldm4(al[mt], aAddr[mt][s16] + stg + 8192u);
            }
#pragma unroll
            for (int q = 0; q < 4; q++) {
                uint32_t t4[4];
                ldm4(t4, bAddr[s16][q] + stg);
                bh[2 * q][0] = t4[0]; bh[2 * q][1] = t4[1];
                bh[2 * q + 1][0] = t4[2]; bh[2 * q + 1][1] = t4[3];
                ldm4(t4, bAddr[s16][q] + stg + 8192u);
                bl[2 * q][0] = t4[0]; bl[2 * q][1] = t4[1];
                bl[2 * q + 1][0] = t4[2]; bl[2 * q + 1][1] = t4[3];
            }
            if (s16 == 1) MBAR_ARRIVE(mb + 8 * (NSTAGE + s));  // release stage
            // three passes so same-accumulator MMAs are far apart
#pragma unroll
            for (int nt = 0; nt < 8; nt++)
#pragma unroll
                for (int mt = 0; mt < 2; mt++)
                    mma16816(acc[mt][nt], ah[mt], bh[nt]);
#pragma unroll
            for (int nt = 0; nt < 8; nt++)
#pragma unroll
                for (int mt = 0; mt < 2; mt++)
                    mma16816(acc[mt][nt], ah[mt], bl[nt]);
#pragma unroll
            for (int nt = 0; nt < 8; nt++)
#pragma unroll
                for (int mt = 0; mt < 2; mt++)
                    mma16816(acc[mt][nt], al[mt], bh[nt]);
        }
    }

    // epilogue
    const int er = wm * 32 + (lid >> 2);
    const int ec = wn * 64 + 2 * (lid & 3);
#pragma unroll
    for (int mt = 0; mt < 2; mt++) {
#pragma unroll
        for (int nt = 0; nt < 8; nt++) {
            float* cp = Cp + (long long)(er + mt * 16) * ldc + ec + nt * 8;
            float2 v0 = make_float2(acc[mt][nt][0], acc[mt][nt][1]);
            float2 v1 = make_float2(acc[mt][nt][2], acc[mt][nt][3]);
            if (ACCUM) {
                float2 o0 = *reinterpret_cast<const float2*>(cp);
                float2 o1 = *reinterpret_cast<const float2*>(cp + 8 * ldc);
                v0.x += o0.x; v0.y += o0.y;
                v1.x += o1.x; v1.y += o1.y;
            }
            *reinterpret_cast<float2*>(cp) = v0;
            *reinterpret_cast<float2*>(cp + 8 * ldc) = v1;
        }
    }
}

// ---------------- RMSNorm ---------------------------------------------------
__global__ __launch_bounds__(256)
void rmsnorm_k(const float* __restrict__ h, const float* __restrict__ w,
               float* __restrict__ out)
{
    const int row = blockIdx.x;
    const float* hr = h + (size_t)row * H_;
    float ss = 0.f;
    for (int j = threadIdx.x; j < H_; j += 256) {
        float x = hr[j];
        ss += x * x;
    }
#pragma unroll
    for (int o = 16; o > 0; o >>= 1) ss += __shfl_xor_sync(0xffffffffu, ss, o);
    __shared__ float sm[8];
    if ((threadIdx.x & 31) == 0) sm[threadIdx.x >> 5] = ss;
    __syncthreads();
    float tot = sm[0];
#pragma unroll
    for (int i = 1; i < 8; i++) tot += sm[i];
    float inv = rsqrtf(tot / (float)H_ + EPS_);
    float* orow = out + (size_t)row * H_;
    for (int j = threadIdx.x; j < H_; j += 256)
        orow[j] = w[j] * hr[j] * inv;
}

// ---------------- RoPE (Q in-place, K roped+packed, V packed + V^T) --------
__global__ __launch_bounds__(HD_)
void rope_pack_k(float* __restrict__ q,
                 const float* __restrict__ kin, const float* __restrict__ vin,
                 const int* __restrict__ pos,
                 const float* __restrict__ cos_t, const float* __restrict__ sin_t,
                 float* __restrict__ keys_l, float* __restrict__ vals_l,
                 float* __restrict__ vt)
{
    const int s = blockIdx.x;
    const int d = threadIdx.x;
    const int p = pos[s];
    const float c  = cos_t[(size_t)p * HD_ + d];
    const float sn = sin_t[(size_t)p * HD_ + d];
    const float sgn = (d < HD_ / 2) ? -1.f : 1.f;

    for (int hh = 0; hh < NH_; hh++) {
        float* qp = q + (size_t)s * H_ + hh * HD_;
        float a = qp[d];
        float b = qp[d ^ (HD_ / 2)];
        __syncthreads();
        qp[d] = a * c + sgn * b * sn;
    }
    for (int kv = 0; kv < NKV_; kv++) {
        const float* kp = kin + (size_t)s * NKV_ * HD_ + kv * HD_;
        const float* vp = vin + (size_t)s * NKV_ * HD_ + kv * HD_;
        float a = kp[d];
        float b = kp[d ^ (HD_ / 2)];
        size_t oidx = (size_t)kv * S_ * HD_ + (size_t)s * HD_ + d;
        float vv = vp[d];
        keys_l[oidx] = a * c + sgn * b * sn;
        vals_l[oidx] = vv;
        vt[((size_t)kv * HD_ + d) * S_ + s] = vv;
    }
}

// ---------------- softmax (scale + mask + softmax) -------------------------
__global__ __launch_bounds__(256)
void softmax_k(float* __restrict__ scores, const float* __restrict__ mask,
               float scale)
{
    const int q = blockIdx.x;
    const int h = blockIdx.y;
    float* row = scores + ((size_t)h * S_ + q) * (size_t)S_;
    const float* m = mask + (size_t)q * S_;

    float v[4];
    float mx = -1e30f;
#pragma unroll
    for (int t = 0; t < 4; t++) {
        int j = threadIdx.x + t * 256;
        v[t] = row[j] * scale + m[j];
        mx = fmaxf(mx, v[t]);
    }
#pragma unroll
    for (int o = 16; o > 0; o >>= 1) mx = fmaxf(mx, __shfl_xor_sync(0xffffffffu, mx, o));
    __shared__ float smx[8];
    __shared__ float ssum[8];
    if ((threadIdx.x & 31) == 0) smx[threadIdx.x >> 5] = mx;
    __syncthreads();
    float rmx = smx[0];
#pragma unroll
    for (int i = 1; i < 8; i++) rmx = fmaxf(rmx, smx[i]);

    float sum = 0.f;
#pragma unroll
    for (int t = 0; t < 4; t++) {
        v[t] = expf(v[t] - rmx);
        sum += v[t];
    }
#pragma unroll
    for (int o = 16; o > 0; o >>= 1) sum += __shfl_xor_sync(0xffffffffu, sum, o);
    if ((threadIdx.x & 31) == 0) ssum[threadIdx.x >> 5] = sum;
    __syncthreads();
    float rsum = ssum[0];
#pragma unroll
    for (int i = 1; i < 8; i++) rsum += ssum[i];
    float inv = 1.f / rsum;
#pragma unroll
    for (int t = 0; t < 4; t++) {
        int j = threadIdx.x + t * 256;
        row[j] = v[t] * inv;
    }
}

// ---------------- silu(gate) * up ------------------------------------------
__global__ __launch_bounds__(256)
void silu_mul_k(float* __restrict__ g, const float* __restrict__ u, long long n)
{
    long long i = (long long)blockIdx.x * 256 + threadIdx.x;
    if (i < n) {
        float x = g[i];
        g[i] = (x / (1.f + expf(-x))) * u[i];
    }
}

// ---------------- launch ----------------------------------------------------
extern "C" void kernel_launch(void* const* d_in, const int* in_sizes, int n_in,
                              void* d_out, int out_size)
{
    const float* x     = (const float*)d_in[0];
    const float* mask  = (const float*)d_in[1];
    const int*   pos   = (const int*)  d_in[2];
    const float* cos_t = (const float*)d_in[3];
    const float* sin_t = (const float*)d_in[4];
    const float* ln1   = (const float*)d_in[5];
    const float* ln2   = (const float*)d_in[6];
    const float* qw    = (const float*)d_in[7];
    const float* kw    = (const float*)d_in[8];
    const float* vw    = (const float*)d_in[9];
    const float* ow    = (const float*)d_in[10];
    const float* gw    = (const float*)d_in[11];
    const float* uw    = (const float*)d_in[12];
    const float* dw    = (const float*)d_in[13];

    float* out  = (float*)d_out;
    float* h    = out;                                   // hidden state lives in d_out
    float* keys = out + (size_t)S_ * H_;                 // [L, NKV, S, HD]
    float* vals = keys + (size_t)L_ * NKV_ * S_ * HD_;   // [L, NKV, S, HD]

    float *n_, *q_, *kv_, *vt_, *sc_, *at_, *ga_, *up_;
    cudaGetSymbolAddress((void**)&n_,  g_n);
    cudaGetSymbolAddress((void**)&q_,  g_q);
    cudaGetSymbolAddress((void**)&kv_, g_kv);
    cudaGetSymbolAddress((void**)&vt_, g_vt);
    cudaGetSymbolAddress((void**)&sc_, g_sc);
    cudaGetSymbolAddress((void**)&at_, g_at);
    cudaGetSymbolAddress((void**)&ga_, g_ga);
    cudaGetSymbolAddress((void**)&up_, g_up);

    cudaFuncSetAttribute(gemm_ws<false>,
                         cudaFuncAttributeMaxDynamicSharedMemorySize, SMEM_DYN);
    cudaFuncSetAttribute(gemm_ws<true>,
                         cudaFuncAttributeMaxDynamicSharedMemorySize, SMEM_DYN);

    const float scale = 1.f / sqrtf((float)HD_);

    cudaMemcpyAsync(h, x, (size_t)S_ * H_ * sizeof(float),
                    cudaMemcpyDeviceToDevice, 0);

    for (int l = 0; l < L_; l++) {
        const float* qwl = qw + (size_t)l * (NH_ * HD_) * H_;
        const float* kwl = kw + (size_t)l * (NKV_ * HD_) * H_;
        const float* vwl = vw + (size_t)l * (NKV_ * HD_) * H_;
        const float* owl = ow + (size_t)l * H_ * (NH_ * HD_);
        const float* gwl = gw + (size_t)l * IS_ * H_;
        const float* uwl = uw + (size_t)l * IS_ * H_;
        const float* dwl = dw + (size_t)l * H_ * IS_;
        float* keys_l = keys + (size_t)l * NKV_ * S_ * HD_;
        float* vals_l = vals + (size_t)l * NKV_ * S_ * HD_;
        float* kscr = kv_;
        float* vscr = kv_ + (size_t)S_ * NKV_ * HD_;

        // ---- attention block ----
        rmsnorm_k<<<S_, 256>>>(h, ln1 + (size_t)l * H_, n_);

        // Q projection
        gemm_ws<false><<<dim3(S_ / 128, H_ / 128, 1), 384, SMEM_DYN>>>(
            n_, H_, 0, qwl, H_, 0, 1, q_, H_, 0, H_, nullptr, nullptr, 0);
        // K + V projections fused (z=0 -> K, z=1 -> V)
        gemm_ws<false><<<dim3(S_ / 128, (NKV_ * HD_) / 128, 2), 384, SMEM_DYN>>>(
            n_, H_, 0, kwl, H_, 0, 1, kscr, NKV_ * HD_, 0, H_,
            vwl, vscr, 1);

        rope_pack_k<<<S_, HD_>>>(q_, kscr, vscr, pos, cos_t, sin_t,
                                 keys_l, vals_l, vt_);

        // scores[h,q,k] = q_h . k_{h/4}   (NT, K = HD)
        gemm_ws<false><<<dim3(S_ / 128, S_ / 128, NH_), 384, SMEM_DYN>>>(
            q_, H_, (long long)HD_,
            keys_l, HD_, (long long)S_ * HD_, NREP_,
            sc_, S_, (long long)S_ * S_, HD_, nullptr, nullptr, 0);

        softmax_k<<<dim3(S_, NH_), 256>>>(sc_, mask, scale);

        // attn_out[q, h*HD+d] = P[h,q,:] . Vt_{h/4}[d,:]  (NT via V^T, K = S)
        gemm_ws<false><<<dim3(S_ / 128, HD_ / 128, NH_), 384, SMEM_DYN>>>(
            sc_, S_, (long long)S_ * S_,
            vt_, S_, (long long)HD_ * S_, NREP_,
            at_, H_, (long long)HD_, S_, nullptr, nullptr, 0);

        // h += attn_out @ o_w^T
        gemm_ws<true><<<dim3(S_ / 128, H_ / 128, 1), 384, SMEM_DYN>>>(
            at_, H_, 0, owl, H_, 0, 1, h, H_, 0, H_, nullptr, nullptr, 0);

        // ---- MLP block ----
        rmsnorm_k<<<S_, 256>>>(h, ln2 + (size_t)l * H_, n_);

        // gate + up fused (z=0 -> gate, z=1 -> up)
        gemm_ws<false><<<dim3(S_ / 128, IS_ / 128, 2), 384, SMEM_DYN>>>(
            n_, H_, 0, gwl, H_, 0, 1, ga_, IS_, 0, H_,
            uwl, up_, 1);

        long long nel = (long long)S_ * IS_;
        silu_mul_k<<<(unsigned)((nel + 255) / 256), 256>>>(ga_, up_, nel);

        // h += act @ down_w^T
        gemm_ws<true><<<dim3(S_ / 128, H_ / 128, 1), 384, SMEM_DYN>>>(
            ga_, IS_, 0, dwl, IS_, 0, 1, h, H_, 0, IS_, nullptr, nullptr, 0);
    }
}

// round 6
// speedup vs baseline: 2.4611x; 1.0235x over previous
#include <cuda_runtime.h>
#include <cuda_bf16.h>
#include <math.h>
#include <stdint.h>

// ---------------- problem constants ----------------
#define S_   1024
#define H_   4096
#define NH_  32
#define NKV_ 8
#define HD_  128
#define NREP_ 4        // NH/NKV
#define IS_  11008
#define L_   2
#define EPS_ 1e-5f

// ---------------- scratch (device globals; no runtime alloc allowed) -------
__device__ float g_n   [(size_t)S_ * H_];                 // rmsnorm output
__device__ float g_q   [(size_t)S_ * H_];                 // Q (pre/post rope)
__device__ float g_kv  [(size_t)2 * S_ * NKV_ * HD_];     // K then V scratch
__device__ float g_vt  [(size_t)NKV_ * HD_ * S_];         // V transposed [kv, d, s]
__device__ float g_sc  [(size_t)NH_ * S_ * S_];           // attention scores (128MB)
__device__ float g_at  [(size_t)S_ * H_];                 // attn output (S, NH*HD)
__device__ float g_ga  [(size_t)S_ * IS_];                // gate
__device__ float g_up  [(size_t)S_ * IS_];                // up

// =================== helpers ===============================================
__device__ __forceinline__ uint32_t smem_u32(const void* p) {
    uint32_t a;
    asm("{ .reg .u64 t; cvta.to.shared.u64 t, %1; cvt.u32.u64 %0, t; }"
        : "=r"(a) : "l"(p));
    return a;
}

__device__ __forceinline__ void ldm4(uint32_t* r, uint32_t addr) {
    asm volatile("ldmatrix.sync.aligned.m8n8.x4.shared.b16 {%0,%1,%2,%3}, [%4];"
        : "=r"(r[0]), "=r"(r[1]), "=r"(r[2]), "=r"(r[3]) : "r"(addr));
}

__device__ __forceinline__ void mma16816(float* c, const uint32_t* a,
                                         const uint32_t* b) {
    asm("mma.sync.aligned.m16n8k16.row.col.f32.bf16.bf16.f32 "
        "{%0,%1,%2,%3}, {%4,%5,%6,%7}, {%8,%9}, {%0,%1,%2,%3};"
        : "+f"(c[0]), "+f"(c[1]), "+f"(c[2]), "+f"(c[3])
        : "r"(a[0]), "r"(a[1]), "r"(a[2]), "r"(a[3]), "r"(b[0]), "r"(b[1]));
}

// split 8 fp32 -> 8 bf16 hi (packed uint4) + 8 bf16 lo (exact residual)
__device__ __forceinline__ void cvt_chunk(float4 f0, float4 f1,
                                          uint4& hi, uint4& lo) {
    float f[8] = {f0.x, f0.y, f0.z, f0.w, f1.x, f1.y, f1.z, f1.w};
    uint32_t h[4], l[4];
#pragma unroll
    for (int i = 0; i < 4; i++) {
        asm("cvt.rn.bf16x2.f32 %0, %1, %2;"
            : "=r"(h[i]) : "f"(f[2 * i + 1]), "f"(f[2 * i]));
        float h0 = __uint_as_float(h[i] << 16);
        float h1 = __uint_as_float(h[i] & 0xffff0000u);
        float r0 = f[2 * i] - h0;
        float r1 = f[2 * i + 1] - h1;
        asm("cvt.rn.bf16x2.f32 %0, %1, %2;"
            : "=r"(l[i]) : "f"(r1), "f"(r0));
    }
    hi = make_uint4(h[0], h[1], h[2], h[3]);
    lo = make_uint4(l[0], l[1], l[2], l[3]);
}

// -------- mbarrier primitives (sm_80-level, valid on compute_103) ----------
#define MBAR_INIT(addr, cnt) \
    asm volatile("mbarrier.init.shared.b64 [%0], %1;" :: "r"(addr), "r"((uint32_t)(cnt)) : "memory")
#define MBAR_ARRIVE(addr) \
    asm volatile("mbarrier.arrive.shared.b64 _, [%0];" :: "r"(addr) : "memory")
#define MBAR_WAIT(mbar_addr, parity) do {                                        \
    uint32_t _m = (uint32_t)(mbar_addr);                                         \
    uint32_t _p = (uint32_t)(parity);                                            \
    uint32_t _done;                                                              \
    asm volatile("{\n\t.reg .pred p;\n\t"                                        \
        "mbarrier.try_wait.parity.acquire.cta.shared::cta.b64 p, [%1], %2;\n\t"  \
        "selp.b32 %0, 1, 0, p;\n\t}"                                             \
        : "=r"(_done) : "r"(_m), "r"(_p) : "memory");                            \
    if (!_done) {                                                                \
        asm volatile("{\n\t.reg .pred P1;\n\t"                                   \
            "WAIT_LOOP_%=:\n\t"                                                  \
            "mbarrier.try_wait.parity.acquire.cta.shared::cta.b64 P1, [%0], %1, 0x989680;\n\t" \
            "@P1 bra.uni WAIT_DONE_%=;\n\t"                                      \
            "bra.uni WAIT_LOOP_%=;\n\t"                                          \
            "WAIT_DONE_%=:\n\t}"                                                 \
            :: "r"(_m), "r"(_p) : "memory");                                     \
    }                                                                            \
} while (0)

// ============ warp-specialized split-bf16 HMMA GEMM ========================
// C[M,N] (+)= A[M,K] * B[N,K]^T. CTA tile 128x128, K-tile 32.
// 12 warps: 0-7 consumers (4x2, warp tile 32x64, mma m16n8k16),
//           8-11 producers (gmem fp32 -> bf16 hi/lo split -> swizzled smem),
//           producer register-double-buffered (prefetch kt+1 over kt's work).
// 4-stage smem ring, 32KB/stage: Ah@0 Al@8192 Bh@16384 Bl@24576.
// flags: bit0 = causal tile skip (return if by > bx)
//        bit1 = bound K to (bx+1)*128 (PV with causal-zero scores)
#define NSTAGE 4
#define STAGE_B 32768
#define SMEM_DYN (NSTAGE * STAGE_B)

struct ProdCtx {
    const float* aRow;
    const float* bRow;
    char* dsm;
    uint32_t mb;
    uint32_t off[4];
};

__device__ __forceinline__ void prod_load(const ProdCtx& cx, int kt,
                                          float4 (&buf)[16]) {
    const float* as = cx.aRow + kt * 32;
    const float* bs = cx.bRow + kt * 32;
#pragma unroll
    for (int i = 0; i < 8; i++) {
        buf[i]     = *reinterpret_cast<const float4*>(as + 4 * i);
        buf[8 + i] = *reinterpret_cast<const float4*>(bs + 4 * i);
    }
}

__device__ __forceinline__ void prod_step(const ProdCtx& cx, int kt, int nkt,
                                          float4 (&cur)[16], float4 (&nxt)[16]) {
    // prefetch next k-tile first: latency hides behind wait + cvt/STS below
    if (kt + 1 < nkt) prod_load(cx, kt + 1, nxt);
    const int s = kt & (NSTAGE - 1);
    const int r = kt >> 2;
    if (r > 0) MBAR_WAIT(cx.mb + 8 * (NSTAGE + s), (r - 1) & 1);
    char* base = cx.dsm + (size_t)s * STAGE_B;
#pragma unroll
    for (int c = 0; c < 4; c++) {
        uint4 hi, lo;
        cvt_chunk(cur[2 * c], cur[2 * c + 1], hi, lo);
        *reinterpret_cast<uint4*>(base + cx.off[c]) = hi;
        *reinterpret_cast<uint4*>(base + 8192 + cx.off[c]) = lo;
    }
#pragma unroll
    for (int c = 0; c < 4; c++) {
        uint4 hi, lo;
        cvt_chunk(cur[8 + 2 * c], cur[9 + 2 * c], hi, lo);
        *reinterpret_cast<uint4*>(base + 16384 + cx.off[c]) = hi;
        *reinterpret_cast<uint4*>(base + 24576 + cx.off[c]) = lo;
    }
    MBAR_ARRIVE(cx.mb + 8 * s);
}

template<bool ACCUM>
__global__ __launch_bounds__(384, 1)
void gemm_ws(const float* __restrict__ A, int lda, long long sAz,
             const float* __restrict__ B, int ldb, long long sBz, int zdiv,
             float* __restrict__ C, int ldc, long long sCz, int K,
             const float* __restrict__ Balt, float* __restrict__ Calt, int altz,
             int flags)
{
    if ((flags & 1) && (int)blockIdx.y > (int)blockIdx.x) return;
    if (flags & 2) {
        int kb = ((int)blockIdx.x + 1) * 128;
        if (kb < K) K = kb;
    }

    extern __shared__ char dsm[];
    __shared__ uint64_t mbar[2 * NSTAGE];   // full[0..3], empty[4..7]
    const uint32_t sb = smem_u32(dsm);
    const uint32_t mb = smem_u32(mbar);
    const int tid = threadIdx.x;
    const int wid = tid >> 5, lid = tid & 31;
    const int z = blockIdx.z;

    int zz = z;
    const float* Bp = B;
    float* Cp = C;
    if (altz && z >= altz) { Bp = Balt; Cp = Calt; zz = z - altz; }

    const float* Ap = A + (long long)blockIdx.x * 128 * lda + (long long)zz * sAz;
    Bp += (long long)blockIdx.y * 128 * ldb + (long long)(zz / zdiv) * sBz;
    Cp += (long long)blockIdx.x * 128 * ldc + (long long)blockIdx.y * 128
        + (long long)zz * sCz;

    if (tid == 0) {
#pragma unroll
        for (int i = 0; i < NSTAGE; i++) {
            MBAR_INIT(mb + 8 * i, 128);             // full: 128 producer threads
            MBAR_INIT(mb + 8 * (NSTAGE + i), 256);  // empty: 256 consumer threads
        }
    }
    __syncthreads();

    const int nkt = K / 32;    // always even for all call sites

    if (wid >= 8) {
        // ================= producer (double-buffered) =================
        const int prow = tid - 256;                 // 0..127
        ProdCtx cx;
        cx.aRow = Ap + (long long)prow * lda;
        cx.bRow = Bp + (long long)prow * ldb;
        cx.dsm = dsm;
        cx.mb = mb;
        const uint32_t rsw = ((uint32_t)(prow >> 1) & 3u);
#pragma unroll
        for (int c = 0; c < 4; c++)
            cx.off[c] = (uint32_t)prow * 64 + (((uint32_t)c ^ rsw) << 4);

        float4 buf0[16], buf1[16];
        prod_load(cx, 0, buf0);
        for (int kt = 0; kt < nkt; kt += 2) {
            prod_step(cx, kt, nkt, buf0, buf1);
            if (kt + 1 < nkt) prod_step(cx, kt + 1, nkt, buf1, buf0);
        }
        return;
    }

    // ================= consumer =================
    const int wm = wid & 3, wn = wid >> 2;
    float acc[2][8][4] = {};

    // ldmatrix lane addresses (stage-0 based)
    uint32_t aAddr[2][2], bAddr[2][4];
    {
        int j = lid >> 3, rin = lid & 7;
#pragma unroll
        for (int mt = 0; mt < 2; mt++) {
#pragma unroll
            for (int s = 0; s < 2; s++) {
                int row = wm * 32 + mt * 16 + (j & 1) * 8 + rin;
                int ch = 2 * s + (j >> 1);
                aAddr[mt][s] = sb + (uint32_t)row * 64
                             + ((uint32_t)(ch ^ ((row >> 1) & 3)) << 4);
            }
        }
#pragma unroll
        for (int q = 0; q < 4; q++) {
#pragma unroll
            for (int s = 0; s < 2; s++) {
                int row = wn * 64 + q * 16 + (j >> 1) * 8 + rin;
                int ch = 2 * s + (j & 1);
                bAddr[s][q] = sb + 16384u + (uint32_t)row * 64
                            + ((uint32_t)(ch ^ ((row >> 1) & 3)) << 4);
            }
        }
    }

    for (int kt = 0; kt < nkt; kt++) {
        const int s = kt & (NSTAGE - 1);
        const uint32_t stg = (uint32_t)s * STAGE_B;
        MBAR_WAIT(mb + 8 * s, (kt >> 2) & 1);

#pragma unroll
        for (int s16 = 0; s16 < 2; s16++) {
            uint32_t ah[2][4], al[2][4], bh[8][2], bl[8][2];
#pragma unroll
            for (int mt = 0; mt < 2; mt++) {
                ldm4(ah[mt], aAddr[mt][s16] + stg);
                ldm4(al[mt], aAddr[mt][s16] + stg + 8192u);
            }
#pragma unroll
            for (int q = 0; q < 4; q++) {
                uint32_t t4[4];
                ldm4(t4, bAddr[s16][q] + stg);
                bh[2 * q][0] = t4[0]; bh[2 * q][1] = t4[1];
                bh[2 * q + 1][0] = t4[2]; bh[2 * q + 1][1] = t4[3];
                ldm4(t4, bAddr[s16][q] + stg + 8192u);
                bl[2 * q][0] = t4[0]; bl[2 * q][1] = t4[1];
                bl[2 * q + 1][0] = t4[2]; bl[2 * q + 1][1] = t4[3];
            }
            if (s16 == 1) MBAR_ARRIVE(mb + 8 * (NSTAGE + s));  // release stage
            // three passes so same-accumulator MMAs are far apart
#pragma unroll
            for (int nt = 0; nt < 8; nt++)
#pragma unroll
                for (int mt = 0; mt < 2; mt++)
                    mma16816(acc[mt][nt], ah[mt], bh[nt]);
#pragma unroll
            for (int nt = 0; nt < 8; nt++)
#pragma unroll
                for (int mt = 0; mt < 2; mt++)
                    mma16816(acc[mt][nt], ah[mt], bl[nt]);
#pragma unroll
            for (int nt = 0; nt < 8; nt++)
#pragma unroll
                for (int mt = 0; mt < 2; mt++)
                    mma16816(acc[mt][nt], al[mt], bh[nt]);
        }
    }

    // epilogue
    const int er = wm * 32 + (lid >> 2);
    const int ec = wn * 64 + 2 * (lid & 3);
#pragma unroll
    for (int mt = 0; mt < 2; mt++) {
#pragma unroll
        for (int nt = 0; nt < 8; nt++) {
            float* cp = Cp + (long long)(er + mt * 16) * ldc + ec + nt * 8;
            float2 v0 = make_float2(acc[mt][nt][0], acc[mt][nt][1]);
            float2 v1 = make_float2(acc[mt][nt][2], acc[mt][nt][3]);
            if (ACCUM) {
                float2 o0 = *reinterpret_cast<const float2*>(cp);
                float2 o1 = *reinterpret_cast<const float2*>(cp + 8 * ldc);
                v0.x += o0.x; v0.y += o0.y;
                v1.x += o1.x; v1.y += o1.y;
            }
            *reinterpret_cast<float2*>(cp) = v0;
            *reinterpret_cast<float2*>(cp + 8 * ldc) = v1;
        }
    }
}

// ---------------- RMSNorm ---------------------------------------------------
__global__ __launch_bounds__(256)
void rmsnorm_k(const float* __restrict__ h, const float* __restrict__ w,
               float* __restrict__ out)
{
    const int row = blockIdx.x;
    const float* hr = h + (size_t)row * H_;
    float ss = 0.f;
    for (int j = threadIdx.x; j < H_; j += 256) {
        float x = hr[j];
        ss += x * x;
    }
#pragma unroll
    for (int o = 16; o > 0; o >>= 1) ss += __shfl_xor_sync(0xffffffffu, ss, o);
    __shared__ float sm[8];
    if ((threadIdx.x & 31) == 0) sm[threadIdx.x >> 5] = ss;
    __syncthreads();
    float tot = sm[0];
#pragma unroll
    for (int i = 1; i < 8; i++) tot += sm[i];
    float inv = rsqrtf(tot / (float)H_ + EPS_);
    float* orow = out + (size_t)row * H_;
    for (int j = threadIdx.x; j < H_; j += 256)
        orow[j] = w[j] * hr[j] * inv;
}

// ---------------- RoPE (Q in-place, K roped+packed, V packed + V^T) --------
__global__ __launch_bounds__(HD_)
void rope_pack_k(float* __restrict__ q,
                 const float* __restrict__ kin, const float* __restrict__ vin,
                 const int* __restrict__ pos,
                 const float* __restrict__ cos_t, const float* __restrict__ sin_t,
                 float* __restrict__ keys_l, float* __restrict__ vals_l,
                 float* __restrict__ vt)
{
    const int s = blockIdx.x;
    const int d = threadIdx.x;
    const int p = pos[s];
    const float c  = cos_t[(size_t)p * HD_ + d];
    const float sn = sin_t[(size_t)p * HD_ + d];
    const float sgn = (d < HD_ / 2) ? -1.f : 1.f;

    for (int hh = 0; hh < NH_; hh++) {
        float* qp = q + (size_t)s * H_ + hh * HD_;
        float a = qp[d];
        float b = qp[d ^ (HD_ / 2)];
        __syncthreads();
        qp[d] = a * c + sgn * b * sn;
    }
    for (int kv = 0; kv < NKV_; kv++) {
        const float* kp = kin + (size_t)s * NKV_ * HD_ + kv * HD_;
        const float* vp = vin + (size_t)s * NKV_ * HD_ + kv * HD_;
        float a = kp[d];
        float b = kp[d ^ (HD_ / 2)];
        size_t oidx = (size_t)kv * S_ * HD_ + (size_t)s * HD_ + d;
        float vv = vp[d];
        keys_l[oidx] = a * c + sgn * b * sn;
        vals_l[oidx] = vv;
        vt[((size_t)kv * HD_ + d) * S_ + s] = vv;
    }
}

// ------- softmax (scale + mask + softmax), causal-bounded row prefix -------
__global__ __launch_bounds__(256)
void softmax_k(float* __restrict__ scores, const float* __restrict__ mask,
               float scale)
{
    const int q = blockIdx.x;
    const int h = blockIdx.y;
    float* row = scores + ((size_t)h * S_ + q) * (size_t)S_;
    const float* m = mask + (size_t)q * S_;
    const int Lq = ((q >> 7) + 1) << 7;    // valid prefix (tile-rounded)
    const int nt = (Lq + 255) >> 8;

    float v[4];
    float mx = -1e30f;
#pragma unroll
    for (int t = 0; t < 4; t++) {
        v[t] = -1e30f;
        if (t < nt) {
            int j = threadIdx.x + t * 256;
            if (j < Lq) {
                v[t] = row[j] * scale + m[j];
                mx = fmaxf(mx, v[t]);
            }
        }
    }
#pragma unroll
    for (int o = 16; o > 0; o >>= 1) mx = fmaxf(mx, __shfl_xor_sync(0xffffffffu, mx, o));
    __shared__ float smx[8];
    __shared__ float ssum[8];
    if ((threadIdx.x & 31) == 0) smx[threadIdx.x >> 5] = mx;
    __syncthreads();
    float rmx = smx[0];
#pragma unroll
    for (int i = 1; i < 8; i++) rmx = fmaxf(rmx, smx[i]);

    float sum = 0.f;
#pragma unroll
    for (int t = 0; t < 4; t++) {
        if (t < nt) {
            int j = threadIdx.x + t * 256;
            if (j < Lq) {
                v[t] = expf(v[t] - rmx);
                sum += v[t];
            }
        }
    }
#pragma unroll
    for (int o = 16; o > 0; o >>= 1) sum += __shfl_xor_sync(0xffffffffu, sum, o);
    if ((threadIdx.x & 31) == 0) ssum[threadIdx.x >> 5] = sum;
    __syncthreads();
    float rsum = ssum[0];
#pragma unroll
    for (int i = 1; i < 8; i++) rsum += ssum[i];
    float inv = 1.f / rsum;
#pragma unroll
    for (int t = 0; t < 4; t++) {
        if (t < nt) {
            int j = threadIdx.x + t * 256;
            if (j < Lq) row[j] = v[t] * inv;
        }
    }
}

// ---------------- silu(gate) * up ------------------------------------------
__global__ __launch_bounds__(256)
void silu_mul_k(float* __restrict__ g, const float* __restrict__ u, long long n)
{
    long long i = (long long)blockIdx.x * 256 + threadIdx.x;
    if (i < n) {
        float x = g[i];
        g[i] = (x / (1.f + expf(-x))) * u[i];
    }
}

// ---------------- launch ----------------------------------------------------
extern "C" void kernel_launch(void* const* d_in, const int* in_sizes, int n_in,
                              void* d_out, int out_size)
{
    const float* x     = (const float*)d_in[0];
    const float* mask  = (const float*)d_in[1];
    const int*   pos   = (const int*)  d_in[2];
    const float* cos_t = (const float*)d_in[3];
    const float* sin_t = (const float*)d_in[4];
    const float* ln1   = (const float*)d_in[5];
    const float* ln2   = (const float*)d_in[6];
    const float* qw    = (const float*)d_in[7];
    const float* kw    = (const float*)d_in[8];
    const float* vw    = (const float*)d_in[9];
    const float* ow    = (const float*)d_in[10];
    const float* gw    = (const float*)d_in[11];
    const float* uw    = (const float*)d_in[12];
    const float* dw    = (const float*)d_in[13];

    float* out  = (float*)d_out;
    float* h    = out;                                   // hidden state lives in d_out
    float* keys = out + (size_t)S_ * H_;                 // [L, NKV, S, HD]
    float* vals = keys + (size_t)L_ * NKV_ * S_ * HD_;   // [L, NKV, S, HD]

    float *n_, *q_, *kv_, *vt_, *sc_, *at_, *ga_, *up_;
    cudaGetSymbolAddress((void**)&n_,  g_n);
    cudaGetSymbolAddress((void**)&q_,  g_q);
    cudaGetSymbolAddress((void**)&kv_, g_kv);
    cudaGetSymbolAddress((void**)&vt_, g_vt);
    cudaGetSymbolAddress((void**)&sc_, g_sc);
    cudaGetSymbolAddress((void**)&at_, g_at);
    cudaGetSymbolAddress((void**)&ga_, g_ga);
    cudaGetSymbolAddress((void**)&up_, g_up);

    cudaFuncSetAttribute(gemm_ws<false>,
                         cudaFuncAttributeMaxDynamicSharedMemorySize, SMEM_DYN);
    cudaFuncSetAttribute(gemm_ws<true>,
                         cudaFuncAttributeMaxDynamicSharedMemorySize, SMEM_DYN);

    const float scale = 1.f / sqrtf((float)HD_);

    cudaMemcpyAsync(h, x, (size_t)S_ * H_ * sizeof(float),
                    cudaMemcpyDeviceToDevice, 0);

    for (int l = 0; l < L_; l++) {
        const float* qwl = qw + (size_t)l * (NH_ * HD_) * H_;
        const float* kwl = kw + (size_t)l * (NKV_ * HD_) * H_;
        const float* vwl = vw + (size_t)l * (NKV_ * HD_) * H_;
        const float* owl = ow + (size_t)l * H_ * (NH_ * HD_);
        const float* gwl = gw + (size_t)l * IS_ * H_;
        const float* uwl = uw + (size_t)l * IS_ * H_;
        const float* dwl = dw + (size_t)l * H_ * IS_;
        float* keys_l = keys + (size_t)l * NKV_ * S_ * HD_;
        float* vals_l = vals + (size_t)l * NKV_ * S_ * HD_;
        float* kscr = kv_;
        float* vscr = kv_ + (size_t)S_ * NKV_ * HD_;

        // ---- attention block ----
        rmsnorm_k<<<S_, 256>>>(h, ln1 + (size_t)l * H_, n_);

        // Q projection
        gemm_ws<false><<<dim3(S_ / 128, H_ / 128, 1), 384, SMEM_DYN>>>(
            n_, H_, 0, qwl, H_, 0, 1, q_, H_, 0, H_, nullptr, nullptr, 0, 0);
        // K + V projections fused (z=0 -> K, z=1 -> V)
        gemm_ws<false><<<dim3(S_ / 128, (NKV_ * HD_) / 128, 2), 384, SMEM_DYN>>>(
            n_, H_, 0, kwl, H_, 0, 1, kscr, NKV_ * HD_, 0, H_,
            vwl, vscr, 1, 0);

        rope_pack_k<<<S_, HD_>>>(q_, kscr, vscr, pos, cos_t, sin_t,
                                 keys_l, vals_l, vt_);

        // scores[h,q,k] = q_h . k_{h/4}   (NT, K = HD), causal tile skip
        gemm_ws<false><<<dim3(S_ / 128, S_ / 128, NH_), 384, SMEM_DYN>>>(
            q_, H_, (long long)HD_,
            keys_l, HD_, (long long)S_ * HD_, NREP_,
            sc_, S_, (long long)S_ * S_, HD_, nullptr, nullptr, 0, 1);

        softmax_k<<<dim3(S_, NH_), 256>>>(sc_, mask, scale);

        // attn_out = P @ V (NT via V^T), K bounded to causal prefix
        gemm_ws<false><<<dim3(S_ / 128, HD_ / 128, NH_), 384, SMEM_DYN>>>(
            sc_, S_, (long long)S_ * S_,
            vt_, S_, (long long)HD_ * S_, NREP_,
            at_, H_, (long long)HD_, S_, nullptr, nullptr, 0, 2);

        // h += attn_out @ o_w^T
        gemm_ws<true><<<dim3(S_ / 128, H_ / 128, 1), 384, SMEM_DYN>>>(
            at_, H_, 0, owl, H_, 0, 1, h, H_, 0, H_, nullptr, nullptr, 0, 0);

        // ---- MLP block ----
        rmsnorm_k<<<S_, 256>>>(h, ln2 + (size_t)l * H_, n_);

        // gate + up fused (z=0 -> gate, z=1 -> up)
        gemm_ws<false><<<dim3(S_ / 128, IS_ / 128, 2), 384, SMEM_DYN>>>(
            n_, H_, 0, gwl, H_, 0, 1, ga_, IS_, 0, H_,
            uwl, up_, 1, 0);

        long long nel = (long long)S_ * IS_;
        silu_mul_k<<<(unsigned)((nel + 255) / 256), 256>>>(ga_, up_, nel);

        // h += act @ down_w^T
        gemm_ws<true><<<dim3(S_ / 128, H_ / 128, 1), 384, SMEM_DYN>>>(
            ga_, IS_, 0, dwl, IS_, 0, 1, h, H_, 0, IS_, nullptr, nullptr, 0, 0);
    }
}

// round 9
// speedup vs baseline: 2.4637x; 1.0011x over previous
#include <cuda_runtime.h>
#include <cuda_bf16.h>
#include <math.h>
#include <stdint.h>

// ---------------- problem constants ----------------
#define S_   1024
#define H_   4096
#define NH_  32
#define NKV_ 8
#define HD_  128
#define NREP_ 4        // NH/NKV
#define IS_  11008
#define L_   2
#define EPS_ 1e-5f

// ---------------- scratch (device globals; no runtime alloc allowed) -------
__device__ float g_inv [4096];                            // per-row inv-rms (2 uses)
__device__ float g_q   [(size_t)S_ * H_];                 // Q (pre/post rope)
__device__ float g_kv  [(size_t)2 * S_ * NKV_ * HD_];     // K then V scratch
__device__ float g_vt  [(size_t)NKV_ * HD_ * S_];         // V transposed [kv, d, s]
__device__ float g_sc  [(size_t)NH_ * S_ * S_];           // attention scores
__device__ float g_at  [(size_t)S_ * H_];                 // attn output (S, NH*HD)
__device__ float g_ga  [(size_t)S_ * IS_];                // gate
__device__ float g_up  [(size_t)S_ * IS_];                // up

// =================== helpers ===============================================
__device__ __forceinline__ uint32_t smem_u32(const void* p) {
    uint32_t a;
    asm("{ .reg .u64 t; cvta.to.shared.u64 t, %1; cvt.u32.u64 %0, t; }"
        : "=r"(a) : "l"(p));
    return a;
}

__device__ __forceinline__ void ldm4(uint32_t* r, uint32_t addr) {
    asm volatile("ldmatrix.sync.aligned.m8n8.x4.shared.b16 {%0,%1,%2,%3}, [%4];"
        : "=r"(r[0]), "=r"(r[1]), "=r"(r[2]), "=r"(r[3]) : "r"(addr));
}

__device__ __forceinline__ void mma16816(float* c, const uint32_t* a,
                                         const uint32_t* b) {
    asm("mma.sync.aligned.m16n8k16.row.col.f32.bf16.bf16.f32 "
        "{%0,%1,%2,%3}, {%4,%5,%6,%7}, {%8,%9}, {%0,%1,%2,%3};"
        : "+f"(c[0]), "+f"(c[1]), "+f"(c[2]), "+f"(c[3])
        : "r"(a[0]), "r"(a[1]), "r"(a[2]), "r"(a[3]), "r"(b[0]), "r"(b[1]));
}

// split 8 fp32 -> 8 bf16 hi (packed uint4) + 8 bf16 lo (exact residual)
__device__ __forceinline__ void cvt_chunk(float4 f0, float4 f1,
                                          uint4& hi, uint4& lo) {
    float f[8] = {f0.x, f0.y, f0.z, f0.w, f1.x, f1.y, f1.z, f1.w};
    uint32_t h[4], l[4];
#pragma unroll
    for (int i = 0; i < 4; i++) {
        asm("cvt.rn.bf16x2.f32 %0, %1, %2;"
            : "=r"(h[i]) : "f"(f[2 * i + 1]), "f"(f[2 * i]));
        float h0 = __uint_as_float(h[i] << 16);
        float h1 = __uint_as_float(h[i] & 0xffff0000u);
        float r0 = f[2 * i] - h0;
        float r1 = f[2 * i + 1] - h1;
        asm("cvt.rn.bf16x2.f32 %0, %1, %2;"
            : "=r"(l[i]) : "f"(r1), "f"(r0));
    }
    hi = make_uint4(h[0], h[1], h[2], h[3]);
    lo = make_uint4(l[0], l[1], l[2], l[3]);
}

// -------- mbarrier primitives (sm_80-level, valid on compute_103) ----------
#define MBAR_INIT(addr, cnt) \
    asm volatile("mbarrier.init.shared.b64 [%0], %1;" :: "r"(addr), "r"((uint32_t)(cnt)) : "memory")
#define MBAR_ARRIVE(addr) \
    asm volatile("mbarrier.arrive.shared.b64 _, [%0];" :: "r"(addr) : "memory")
#define MBAR_WAIT(mbar_addr, parity) do {                                        \
    uint32_t _m = (uint32_t)(mbar_addr);                                         \
    uint32_t _p = (uint32_t)(parity);                                            \
    uint32_t _done;                                                              \
    asm volatile("{\n\t.reg .pred p;\n\t"                                        \
        "mbarrier.try_wait.parity.acquire.cta.shared::cta.b64 p, [%1], %2;\n\t"  \
        "selp.b32 %0, 1, 0, p;\n\t}"                                             \
        : "=r"(_done) : "r"(_m), "r"(_p) : "memory");                            \
    if (!_done) {                                                                \
        asm volatile("{\n\t.reg .pred P1;\n\t"                                   \
            "WAIT_LOOP_%=:\n\t"                                                  \
            "mbarrier.try_wait.parity.acquire.cta.shared::cta.b64 P1, [%0], %1, 0x989680;\n\t" \
            "@P1 bra.uni WAIT_DONE_%=;\n\t"                                      \
            "bra.uni WAIT_LOOP_%=;\n\t"                                          \
            "WAIT_DONE_%=:\n\t}"                                                 \
            :: "r"(_m), "r"(_p) : "memory");                                     \
    }                                                                            \
} while (0)

// ============ warp-specialized split-bf16 HMMA GEMM ========================
// C[M,N] (+)= A[M,K] * B[N,K]^T. CTA tile 128x128, K-tile 32, 4-stage ring.
// 12 warps: 0-7 consumers (4x2 warp grid), 8-11 producers.
// y-sections: up to 3 (B,C,ldb,ldc) triples partitioned along grid.y.
// nsplit>1: grid.z = K-chunk index, epilogue = atomicAdd into C.
// flags: 1 = causal tile skip; 2 = bound K to (bx+1)*128.
// NORM: if w != null, A loads scaled by inv[row]*w[k] (fused rmsnorm).
#define NSTAGE 4
#define STAGE_B 32768
#define SMEM_DYN (NSTAGE * STAGE_B)

struct GP {
    const float* A; int lda; long long sAz;
    const float* B0; float* C0; int ldb0, ldc0;
    const float* B1; float* C1; int ldb1, ldc1;
    const float* B2; float* C2; int ldb2, ldc2;
    int y1, y2;
    long long sBz, sCz; int zdiv;
    int K; int nsplit; int flags;
    const float* w; const float* inv;
};

__device__ __forceinline__ void prod_load(const float* aRow, const float* bRow,
                                          int kt, float4 (&buf)[16]) {
    const float* as = aRow + kt * 32;
    const float* bs = bRow + kt * 32;
#pragma unroll
    for (int i = 0; i < 8; i++) {
        buf[i]     = *reinterpret_cast<const float4*>(as + 4 * i);
        buf[8 + i] = *reinterpret_cast<const float4*>(bs + 4 * i);
    }
}

__device__ __forceinline__ void prod_step(const float* aRow, const float* bRow,
                                          char* dsm, uint32_t mb,
                                          const uint32_t* off,
                                          const float* wb, float rs,
                                          int kt, int nkt,
                                          float4 (&cur)[16], float4 (&nxt)[16]) {
    if (kt + 1 < nkt) prod_load(aRow, bRow, kt + 1, nxt);
    const int s = kt & (NSTAGE - 1);
    const int r = kt >> 2;
    if (r > 0) MBAR_WAIT(mb + 8 * (NSTAGE + s), (r - 1) & 1);
    if (wb) {
        const float4* wv = reinterpret_cast<const float4*>(wb + kt * 32);
#pragma unroll
        for (int i = 0; i < 8; i++) {
            float4 wz = wv[i];
            cur[i].x *= rs * wz.x; cur[i].y *= rs * wz.y;
            cur[i].z *= rs * wz.z; cur[i].w *= rs * wz.w;
        }
    }
    char* base = dsm + (size_t)s * STAGE_B;
#pragma unroll
    for (int c = 0; c < 4; c++) {
        uint4 hi, lo;
        cvt_chunk(cur[2 * c], cur[2 * c + 1], hi, lo);
        *reinterpret_cast<uint4*>(base + off[c]) = hi;
        *reinterpret_cast<uint4*>(base + 8192 + off[c]) = lo;
    }
#pragma unroll
    for (int c = 0; c < 4; c++) {
        uint4 hi, lo;
        cvt_chunk(cur[8 + 2 * c], cur[9 + 2 * c], hi, lo);
        *reinterpret_cast<uint4*>(base + 16384 + off[c]) = hi;
        *reinterpret_cast<uint4*>(base + 24576 + off[c]) = lo;
    }
    MBAR_ARRIVE(mb + 8 * s);
}

__global__ __launch_bounds__(384, 1)
void gemm_ws(GP p)
{
    const int bx = blockIdx.x;
    const int byg = blockIdx.y;
    if ((p.flags & 1) && byg > bx) return;
    int K = p.K;
    if (p.flags & 2) {
        int kb = (bx + 1) * 128;
        if (kb < K) K = kb;
    }

    // y-section select
    const float* B; float* C; int ldb, ldc; int by = byg;
    if (byg >= p.y2)      { B = p.B2; C = p.C2; ldb = p.ldb2; ldc = p.ldc2; by = byg - p.y2; }
    else if (byg >= p.y1) { B = p.B1; C = p.C1; ldb = p.ldb1; ldc = p.ldc1; by = byg - p.y1; }
    else                  { B = p.B0; C = p.C0; ldb = p.ldb0; ldc = p.ldc0; }

    int split = 0, zz = blockIdx.z;
    if (p.nsplit > 1) { split = blockIdx.z; zz = 0; }
    const int nktT = K / 32;
    const int kt0 = (nktT * split) / p.nsplit;
    const int kt1 = (nktT * (split + 1)) / p.nsplit;
    const int nkt = kt1 - kt0;

    const float* Ap = p.A + (long long)bx * 128 * p.lda + (long long)zz * p.sAz + kt0 * 32;
    const float* Bp = B + (long long)by * 128 * ldb + (long long)(zz / p.zdiv) * p.sBz + kt0 * 32;
    float* Cp = C + (long long)bx * 128 * ldc + (long long)by * 128 + (long long)zz * p.sCz;

    extern __shared__ char dsm[];
    __shared__ uint64_t mbar[2 * NSTAGE];
    const uint32_t sb = smem_u32(dsm);
    const uint32_t mb = smem_u32(mbar);
    const int tid = threadIdx.x;
    const int wid = tid >> 5, lid = tid & 31;

    if (tid == 0) {
#pragma unroll
        for (int i = 0; i < NSTAGE; i++) {
            MBAR_INIT(mb + 8 * i, 128);
            MBAR_INIT(mb + 8 * (NSTAGE + i), 256);
        }
    }
    __syncthreads();

    if (wid >= 8) {
        // ================= producer =================
        const int prow = tid - 256;
        const float* aRow = Ap + (long long)prow * p.lda;
        const float* bRow = Bp + (long long)prow * ldb;
        float rs = 0.f;
        const float* wb = nullptr;
        if (p.w) { rs = p.inv[bx * 128 + prow]; wb = p.w + kt0 * 32; }
        const uint32_t rsw = ((uint32_t)(prow >> 1) & 3u);
        uint32_t off[4];
#pragma unroll
        for (int c = 0; c < 4; c++)
            off[c] = (uint32_t)prow * 64 + (((uint32_t)c ^ rsw) << 4);

        float4 buf0[16], buf1[16];
        prod_load(aRow, bRow, 0, buf0);
        for (int kt = 0; kt < nkt; kt += 2) {
            prod_step(aRow, bRow, dsm, mb, off, wb, rs, kt, nkt, buf0, buf1);
            if (kt + 1 < nkt)
                prod_step(aRow, bRow, dsm, mb, off, wb, rs, kt + 1, nkt, buf1, buf0);
        }
        return;
    }

    // ================= consumer =================
    const int wm = wid & 3, wn = wid >> 2;
    float acc[2][8][4] = {};

    uint32_t aAddr[2][2], bAddr[2][4];
    {
        int j = lid >> 3, rin = lid & 7;
#pragma unroll
        for (int mt = 0; mt < 2; mt++) {
#pragma unroll
            for (int s = 0; s < 2; s++) {
                int row = wm * 32 + mt * 16 + (j & 1) * 8 + rin;
                int ch = 2 * s + (j >> 1);
                aAddr[mt][s] = sb + (uint32_t)row * 64
                             + ((uint32_t)(ch ^ ((row >> 1) & 3)) << 4);
            }
        }
#pragma unroll
        for (int q = 0; q < 4; q++) {
#pragma unroll
            for (int s = 0; s < 2; s++) {
                int row = wn * 64 + q * 16 + (j >> 1) * 8 + rin;
                int ch = 2 * s + (j & 1);
                bAddr[s][q] = sb + 16384u + (uint32_t)row * 64
                            + ((uint32_t)(ch ^ ((row >> 1) & 3)) << 4);
            }
        }
    }

    for (int kt = 0; kt < nkt; kt++) {
        const int s = kt & (NSTAGE - 1);
        const uint32_t stg = (uint32_t)s * STAGE_B;
        MBAR_WAIT(mb + 8 * s, (kt >> 2) & 1);

#pragma unroll
        for (int s16 = 0; s16 < 2; s16++) {
            uint32_t ah[2][4], al[2][4], bh[8][2], bl[8][2];
#pragma unroll
            for (int mt = 0; mt < 2; mt++) {
                ldm4(ah[mt], aAddr[mt][s16] + stg);
                ldm4(al[mt], aAddr[mt][s16] + stg + 8192u);
            }
#pragma unroll
            for (int q = 0; q < 4; q++) {
                uint32_t t4[4];
                ldm4(t4, bAddr[s16][q] + stg);
                bh[2 * q][0] = t4[0]; bh[2 * q][1] = t4[1];
                bh[2 * q + 1][0] = t4[2]; bh[2 * q + 1][1] = t4[3];
                ldm4(t4, bAddr[s16][q] + stg + 8192u);
                bl[2 * q][0] = t4[0]; bl[2 * q][1] = t4[1];
                bl[2 * q + 1][0] = t4[2]; bl[2 * q + 1][1] = t4[3];
            }
            if (s16 == 1) MBAR_ARRIVE(mb + 8 * (NSTAGE + s));
#pragma unroll
            for (int nt = 0; nt < 8; nt++)
#pragma unroll
                for (int mt = 0; mt < 2; mt++)
                    mma16816(acc[mt][nt], ah[mt], bh[nt]);
#pragma unroll
            for (int nt = 0; nt < 8; nt++)
#pragma unroll
                for (int mt = 0; mt < 2; mt++)
                    mma16816(acc[mt][nt], ah[mt], bl[nt]);
#pragma unroll
            for (int nt = 0; nt < 8; nt++)
#pragma unroll
                for (int mt = 0; mt < 2; mt++)
                    mma16816(acc[mt][nt], al[mt], bh[nt]);
        }
    }

    // epilogue
    const int er = wm * 32 + (lid >> 2);
    const int ec = wn * 64 + 2 * (lid & 3);
    if (p.nsplit > 1) {
#pragma unroll
        for (int mt = 0; mt < 2; mt++) {
#pragma unroll
            for (int nt = 0; nt < 8; nt++) {
                float* cp = Cp + (long long)(er + mt * 16) * ldc + ec + nt * 8;
                atomicAdd(cp + 0, acc[mt][nt][0]);
                atomicAdd(cp + 1, acc[mt][nt][1]);
                atomicAdd(cp + 8 * (long long)ldc + 0, acc[mt][nt][2]);
                atomicAdd(cp + 8 * (long long)ldc + 1, acc[mt][nt][3]);
            }
        }
    } else {
#pragma unroll
        for (int mt = 0; mt < 2; mt++) {
#pragma unroll
            for (int nt = 0; nt < 8; nt++) {
                float* cp = Cp + (long long)(er + mt * 16) * ldc + ec + nt * 8;
                *reinterpret_cast<float2*>(cp) =
                    make_float2(acc[mt][nt][0], acc[mt][nt][1]);
                *reinterpret_cast<float2*>(cp + 8 * (long long)ldc) =
                    make_float2(acc[mt][nt][2], acc[mt][nt][3]);
            }
        }
    }
}

// ---------------- inv-rms per row (rmsnorm folded into GEMM producers) -----
__global__ __launch_bounds__(256)
void invnorm_k(const float* __restrict__ h, float* __restrict__ inv)
{
    const int row = blockIdx.x * 8 + (threadIdx.x >> 5);
    const int lane = threadIdx.x & 31;
    const float4* hr = reinterpret_cast<const float4*>(h + (size_t)row * H_);
    float ss = 0.f;
#pragma unroll
    for (int i = 0; i < 32; i++) {
        float4 v = hr[lane + i * 32];
        ss += v.x * v.x + v.y * v.y + v.z * v.z + v.w * v.w;
    }
#pragma unroll
    for (int o = 16; o > 0; o >>= 1) ss += __shfl_xor_sync(0xffffffffu, ss, o);
    if (lane == 0) inv[row] = rsqrtf(ss / (float)H_ + EPS_);
}

// ---------------- RoPE (no syncthreads; Q pre-scaled by 1/sqrt(HD)) --------
__global__ __launch_bounds__(256)
void rope_k(float* __restrict__ q,
            const float* __restrict__ kin, const float* __restrict__ vin,
            const int* __restrict__ pos,
            const float* __restrict__ cosT, const float* __restrict__ sinT,
            float* __restrict__ keys_l, float* __restrict__ vals_l,
            float* __restrict__ vt, float scale)
{
    const int s = blockIdx.x;
    const int p = pos[s];
    const float* cb = cosT + (size_t)p * HD_;
    const float* sb = sinT + (size_t)p * HD_;

    // Q: NH*64 = 2048 pairs, 8 per thread; each thread owns both halves.
#pragma unroll
    for (int i = 0; i < 8; i++) {
        int pi = threadIdx.x + i * 256;
        int hh = pi >> 6, d = pi & 63;
        float c0 = cb[d], c1 = cb[d + 64], s0 = sb[d], s1 = sb[d + 64];
        float* qp = q + (size_t)s * H_ + hh * HD_;
        float a = qp[d], b = qp[d + 64];
        qp[d]      = (a * c0 - b * s0) * scale;
        qp[d + 64] = (b * c1 + a * s1) * scale;
    }
    // K rope + pack, V pack + transpose: NKV*64 = 512 pairs, 2 per thread.
#pragma unroll
    for (int i = 0; i < 2; i++) {
        int pi = threadIdx.x + i * 256;
        int kv = pi >> 6, d = pi & 63;
        float c0 = cb[d], c1 = cb[d + 64], s0 = sb[d], s1 = sb[d + 64];
        const float* kp = kin + (size_t)s * (NKV_ * HD_) + kv * HD_;
        const float* vp = vin + (size_t)s * (NKV_ * HD_) + kv * HD_;
        float a = kp[d], b = kp[d + 64];
        size_t ob = (size_t)kv * S_ * HD_ + (size_t)s * HD_;
        keys_l[ob + d]      = a * c0 - b * s0;
        keys_l[ob + d + 64] = b * c1 + a * s1;
        float v0 = vp[d], v1 = vp[d + 64];
        vals_l[ob + d] = v0;
        vals_l[ob + d + 64] = v1;
        vt[((size_t)kv * HD_ + d) * S_ + s] = v0;
        vt[((size_t)kv * HD_ + d + 64) * S_ + s] = v1;
    }
}

// ------- softmax (mask + softmax; scale pre-folded into Q), causal prefix --
__global__ __launch_bounds__(256)
void softmax_k(float* __restrict__ scores, const float* __restrict__ mask)
{
    const int q = blockIdx.x;
    const int h = blockIdx.y;
    float* row = scores + ((size_t)h * S_ + q) * (size_t)S_;
    const float* m = mask + (size_t)q * S_;
    const int Lq = ((q >> 7) + 1) << 7;
    const int nt = (Lq + 255) >> 8;

    float v[4];
    float mx = -1e30f;
#pragma unroll
    for (int t = 0; t < 4; t++) {
        v[t] = -1e30f;
        if (t < nt) {
            int j = threadIdx.x + t * 256;
            if (j < Lq) {
                v[t] = row[j] + m[j];
                mx = fmaxf(mx, v[t]);
            }
        }
    }
#pragma unroll
    for (int o = 16; o > 0; o >>= 1) mx = fmaxf(mx, __shfl_xor_sync(0xffffffffu, mx, o));
    __shared__ float smx[8];
    __shared__ float ssum[8];
    if ((threadIdx.x & 31) == 0) smx[threadIdx.x >> 5] = mx;
    __syncthreads();
    float rmx = smx[0];
#pragma unroll
    for (int i = 1; i < 8; i++) rmx = fmaxf(rmx, smx[i]);

    float sum = 0.f;
#pragma unroll
    for (int t = 0; t < 4; t++) {
        if (t < nt) {
            int j = threadIdx.x + t * 256;
            if (j < Lq) {
                v[t] = expf(v[t] - rmx);
                sum += v[t];
            }
        }
    }
#pragma unroll
    for (int o = 16; o > 0; o >>= 1) sum += __shfl_xor_sync(0xffffffffu, sum, o);
    if ((threadIdx.x & 31) == 0) ssum[threadIdx.x >> 5] = sum;
    __syncthreads();
    float rsum = ssum[0];
#pragma unroll
    for (int i = 1; i < 8; i++) rsum += ssum[i];
    float inv = 1.f / rsum;
#pragma unroll
    for (int t = 0; t < 4; t++) {
        if (t < nt) {
            int j = threadIdx.x + t * 256;
            if (j < Lq) row[j] = v[t] * inv;
        }
    }
}

// ---------------- silu(gate) * up ------------------------------------------
__global__ __launch_bounds__(256)
void silu_mul_k(float* __restrict__ g, const float* __restrict__ u, long long n)
{
    long long i = (long long)blockIdx.x * 256 + threadIdx.x;
    if (i < n) {
        float x = g[i];
        g[i] = (x / (1.f + expf(-x))) * u[i];
    }
}

// ---------------- launch ----------------------------------------------------
extern "C" void kernel_launch(void* const* d_in, const int* in_sizes, int n_in,
                              void* d_out, int out_size)
{
    const float* x     = (const float*)d_in[0];
    const float* mask  = (const float*)d_in[1];
    const int*   pos   = (const int*)  d_in[2];
    const float* cos_t = (const float*)d_in[3];
    const float* sin_t = (const float*)d_in[4];
    const float* ln1   = (const float*)d_in[5];
    const float* ln2   = (const float*)d_in[6];
    const float* qw    = (const float*)d_in[7];
    const float* kw    = (const float*)d_in[8];
    const float* vw    = (const float*)d_in[9];
    const float* ow    = (const float*)d_in[10];
    const float* gw    = (const float*)d_in[11];
    const float* uw    = (const float*)d_in[12];
    const float* dw    = (const float*)d_in[13];

    float* out  = (float*)d_out;
    float* h    = out;
    float* keys = out + (size_t)S_ * H_;
    float* vals = keys + (size_t)L_ * NKV_ * S_ * HD_;

    float *inv_, *q_, *kv_, *vt_, *sc_, *at_, *ga_, *up_;
    cudaGetSymbolAddress((void**)&inv_, g_inv);
    cudaGetSymbolAddress((void**)&q_,  g_q);
    cudaGetSymbolAddress((void**)&kv_, g_kv);
    cudaGetSymbolAddress((void**)&vt_, g_vt);
    cudaGetSymbolAddress((void**)&sc_, g_sc);
    cudaGetSymbolAddress((void**)&at_, g_at);
    cudaGetSymbolAddress((void**)&ga_, g_ga);
    cudaGetSymbolAddress((void**)&up_, g_up);

    cudaFuncSetAttribute(gemm_ws,
                         cudaFuncAttributeMaxDynamicSharedMemorySize, SMEM_DYN);

    const float scale = 1.f / sqrtf((float)HD_);
    const int BIG = 1 << 30;

    cudaMemcpyAsync(h, x, (size_t)S_ * H_ * sizeof(float),
                    cudaMemcpyDeviceToDevice, 0);

    for (int l = 0; l < L_; l++) {
        const float* qwl = qw + (size_t)l * (NH_ * HD_) * H_;
        const float* kwl = kw + (size_t)l * (NKV_ * HD_) * H_;
        const float* vwl = vw + (size_t)l * (NKV_ * HD_) * H_;
        const float* owl = ow + (size_t)l * H_ * (NH_ * HD_);
        const float* gwl = gw + (size_t)l * IS_ * H_;
        const float* uwl = uw + (size_t)l * IS_ * H_;
        const float* dwl = dw + (size_t)l * H_ * IS_;
        float* keys_l = keys + (size_t)l * NKV_ * S_ * HD_;
        float* vals_l = vals + (size_t)l * NKV_ * S_ * HD_;
        float* kscr = kv_;
        float* vscr = kv_ + (size_t)S_ * NKV_ * HD_;

        // ---- attention block ----
        invnorm_k<<<S_ / 8, 256>>>(h, inv_);

        // fused QKV projection, split-K x3, atomic epilogue, fused rmsnorm
        cudaMemsetAsync(q_,  0, (size_t)S_ * H_ * sizeof(float), 0);
        cudaMemsetAsync(kv_, 0, (size_t)2 * S_ * NKV_ * HD_ * sizeof(float), 0);
        {
            GP p = {};
            p.A = h; p.lda = H_; p.sAz = 0;
            p.B0 = qwl; p.C0 = q_;   p.ldb0 = H_; p.ldc0 = H_;
            p.B1 = kwl; p.C1 = kscr; p.ldb1 = H_; p.ldc1 = NKV_ * HD_;
            p.B2 = vwl; p.C2 = vscr; p.ldb2 = H_; p.ldc2 = NKV_ * HD_;
            p.y1 = 32; p.y2 = 40;
            p.sBz = 0; p.sCz = 0; p.zdiv = 1;
            p.K = H_; p.nsplit = 3; p.flags = 0;
            p.w = ln1 + (size_t)l * H_; p.inv = inv_;
            gemm_ws<<<dim3(8, 48, 3), 384, SMEM_DYN>>>(p);
        }

        rope_k<<<S_, 256>>>(q_, kscr, vscr, pos, cos_t, sin_t,
                            keys_l, vals_l, vt_, scale);

        // scores = q . k (causal tile skip); q pre-scaled
        {
            GP p = {};
            p.A = q_; p.lda = H_; p.sAz = HD_;
            p.B0 = keys_l; p.C0 = sc_; p.ldb0 = HD_; p.ldc0 = S_;
            p.y1 = BIG; p.y2 = BIG;
            p.sBz = (long long)S_ * HD_; p.sCz = (long long)S_ * S_; p.zdiv = NREP_;
            p.K = HD_; p.nsplit = 1; p.flags = 1;
            gemm_ws<<<dim3(8, 8, NH_), 384, SMEM_DYN>>>(p);
        }

        softmax_k<<<dim3(S_, NH_), 256>>>(sc_, mask);

        // attn_out = P @ V (via V^T), K bounded to causal prefix
        {
            GP p = {};
            p.A = sc_; p.lda = S_; p.sAz = (long long)S_ * S_;
            p.B0 = vt_; p.C0 = at_; p.ldb0 = S_; p.ldc0 = H_;
            p.y1 = BIG; p.y2 = BIG;
            p.sBz = (long long)HD_ * S_; p.sCz = HD_; p.zdiv = NREP_;
            p.K = S_; p.nsplit = 1; p.flags = 2;
            gemm_ws<<<dim3(8, 1, NH_), 384, SMEM_DYN>>>(p);
        }

        // h += attn_out @ o_w^T  (split-K x4, atomics into h)
        {
            GP p = {};
            p.A = at_; p.lda = H_; p.sAz = 0;
            p.B0 = owl; p.C0 = h; p.ldb0 = H_; p.ldc0 = H_;
            p.y1 = BIG; p.y2 = BIG;
            p.sBz = 0; p.sCz = 0; p.zdiv = 1;
            p.K = H_; p.nsplit = 4; p.flags = 0;
            gemm_ws<<<dim3(8, 32, 4), 384, SMEM_DYN>>>(p);
        }

        // ---- MLP block ----
        invnorm_k<<<S_ / 8, 256>>>(h, inv_ + 2048);

        cudaMemsetAsync(ga_, 0, (size_t)S_ * IS_ * sizeof(float), 0);
        cudaMemsetAsync(up_, 0, (size_t)S_ * IS_ * sizeof(float), 0);
        {
            GP p = {};
            p.A = h; p.lda = H_; p.sAz = 0;
            p.B0 = gwl; p.C0 = ga_; p.ldb0 = H_; p.ldc0 = IS_;
            p.B1 = uwl; p.C1 = up_; p.ldb1 = H_; p.ldc1 = IS_;
            p.y1 = 86; p.y2 = BIG;
            p.sBz = 0; p.sCz = 0; p.zdiv = 1;
            p.K = H_; p.nsplit = 2; p.flags = 0;
            p.w = ln2 + (size_t)l * H_; p.inv = inv_ + 2048;
            gemm_ws<<<dim3(8, 172, 2), 384, SMEM_DYN>>>(p);
        }

        long long nel = (long long)S_ * IS_;
        silu_mul_k<<<(unsigned)((nel + 255) / 256), 256>>>(ga_, up_, nel);

        // h += act @ down_w^T  (split-K x4, atomics into h)
        {
            GP p = {};
            p.A = ga_; p.lda = IS_; p.sAz = 0;
            p.B0 = dwl; p.C0 = h; p.ldb0 = IS_; p.ldc0 = H_;
            p.y1 = BIG; p.y2 = BIG;
            p.sBz = 0; p.sCz = 0; p.zdiv = 1;
            p.K = IS_; p.nsplit = 4; p.flags = 0;
            gemm_ws<<<dim3(8, 32, 4), 384, SMEM_DYN>>>(p);
        }
    }
}